// round 13
// baseline (speedup 1.0000x reference)
#include <cuda_runtime.h>
#include <cuda_bf16.h>
#include <math.h>
#include <stdint.h>

// ---------------------------------------------------------------------------
// Problem constants (B=1, S=2048, D=4096, n_head=32, kv_head=8, hd=128)
// ---------------------------------------------------------------------------
#define S_LEN 2048
#define D_MODEL 4096
#define GS_DIM 1024
#define N_HEAD 32
#define KV_HEAD 8
#define HEAD_DIM 128
#define GVS 64

// fp32 scratch
__device__ float g_Q[S_LEN * D_MODEL];
__device__ float g_K[S_LEN * GS_DIM];
__device__ float2 g_tab[S_LEN * GVS];

// bf16 hi/lo splits
__device__ __nv_bfloat16 g_xh[S_LEN * D_MODEL],  g_xl[S_LEN * D_MODEL];
__device__ __nv_bfloat16 g_yh[S_LEN * D_MODEL],  g_yl[S_LEN * D_MODEL];
__device__ __nv_bfloat16 g_Wqh[D_MODEL * D_MODEL], g_Wql[D_MODEL * D_MODEL];
__device__ __nv_bfloat16 g_Wkh[D_MODEL * GS_DIM],  g_Wkl[D_MODEL * GS_DIM];
__device__ __nv_bfloat16 g_Wvh[D_MODEL * GS_DIM],  g_Wvl[D_MODEL * GS_DIM];
__device__ __nv_bfloat16 g_Woh[D_MODEL * D_MODEL], g_Wol[D_MODEL * D_MODEL];
__device__ __nv_bfloat16 g_AOh[S_LEN * D_MODEL],   g_AOl[S_LEN * D_MODEL];
__device__ __nv_bfloat16 g_Qh[S_LEN * D_MODEL],    g_Ql[S_LEN * D_MODEL];
__device__ __nv_bfloat16 g_Kh[S_LEN * GS_DIM],     g_Kl[S_LEN * GS_DIM];
__device__ __nv_bfloat16 g_Vh[S_LEN * GS_DIM],     g_Vl[S_LEN * GS_DIM];

// ---------------------------------------------------------------------------
// Mega-split: all 6 fp32->bf16 hi/lo conversions in one launch
// ---------------------------------------------------------------------------
struct SplitArgs {
    const float* src[6];
    __nv_bfloat16* hi[6];
    __nv_bfloat16* lo[6];
    int off[7];
};

__global__ void mega_split_kernel(SplitArgs a)
{
    int i = blockIdx.x * blockDim.x + threadIdx.x;
    if (i >= a.off[6]) return;
    int s = 0;
#pragma unroll
    for (int t = 1; t < 6; t++) s += (i >= a.off[t]);
    int j = i - a.off[s];
    float v = a.src[s][j];
    __nv_bfloat16 h = __float2bfloat16(v);
    a.hi[s][j] = h;
    a.lo[s][j] = __float2bfloat16(v - __bfloat162float(h));
}

// ---------------------------------------------------------------------------
// MMA helpers
// ---------------------------------------------------------------------------
__device__ __forceinline__ void ldmx4(uint32_t* r, const void* p)
{
    uint32_t a = (uint32_t)__cvta_generic_to_shared(p);
    asm volatile("ldmatrix.sync.aligned.m8n8.x4.shared.b16 {%0,%1,%2,%3}, [%4];"
                 : "=r"(r[0]), "=r"(r[1]), "=r"(r[2]), "=r"(r[3]) : "r"(a));
}
__device__ __forceinline__ void ldmx4t(uint32_t* r, const void* p)
{
    uint32_t a = (uint32_t)__cvta_generic_to_shared(p);
    asm volatile("ldmatrix.sync.aligned.m8n8.x4.trans.shared.b16 {%0,%1,%2,%3}, [%4];"
                 : "=r"(r[0]), "=r"(r[1]), "=r"(r[2]), "=r"(r[3]) : "r"(a));
}
__device__ __forceinline__ void mma16816(float* d, const uint32_t* a,
                                         uint32_t b0, uint32_t b1)
{
    asm volatile(
        "mma.sync.aligned.m16n8k16.row.col.f32.bf16.bf16.f32 "
        "{%0,%1,%2,%3}, {%4,%5,%6,%7}, {%8,%9}, {%0,%1,%2,%3};"
        : "+f"(d[0]), "+f"(d[1]), "+f"(d[2]), "+f"(d[3])
        : "r"(a[0]), "r"(a[1]), "r"(a[2]), "r"(a[3]), "r"(b0), "r"(b1));
}
__device__ __forceinline__ void cpasync16(void* smem, const void* gmem)
{
    uint32_t a = (uint32_t)__cvta_generic_to_shared(smem);
    asm volatile("cp.async.cg.shared.global [%0], [%1], 16;" :: "r"(a), "l"(gmem));
}
#define CP_COMMIT() asm volatile("cp.async.commit_group;")
#define CP_WAIT1()  asm volatile("cp.async.wait_group 1;")

// ---------------------------------------------------------------------------
// Split-bf16 3-pass GEMM tile: CTA 256x128, BK=32, 8 warps of 64x64.
// Double-buffered cp.async. Output fp32 (C) or split bf16 (Ch/Cl if C==null).
// ---------------------------------------------------------------------------
#define BM 256
#define BN 128
#define BK 32
#define A_STRIDE 40
#define B_STRIDE 136
#define ASZ (BM * A_STRIDE)
#define BSZ (BK * B_STRIDE)
#define STG (2 * ASZ + 2 * BSZ)
#define GEMM_SMEM (2 * STG * 2)   // bytes (~117 KB)

__device__ __forceinline__ void gemm_tile(
    const __nv_bfloat16* __restrict__ Ah, const __nv_bfloat16* __restrict__ Al,
    const __nv_bfloat16* __restrict__ Bh, const __nv_bfloat16* __restrict__ Bl,
    const float* __restrict__ bias,
    float* __restrict__ C, __nv_bfloat16* __restrict__ Ch,
    __nv_bfloat16* __restrict__ Cl,
    int N, int K, int m0, int n0, __nv_bfloat16* sm)
{
    const int tid  = threadIdx.x;
    const int lane = tid & 31;
    const int wid  = tid >> 5;
    const int wm   = (wid >> 1) * 64;    // 0,64,128,192
    const int wn   = (wid & 1) * 64;     // 0,64

    // A staging: thread tid loads row tid, 4 chunks of 8 (cols 0,8,16,24)
    // B staging: 512 chunks, 2 per thread (rows 0..15 and 16..31)
    const int br0 = tid >> 4, bc0 = (tid & 15) * 8;
    const int br1 = br0 + 16;

    float acc[4][8][4];
#pragma unroll
    for (int i = 0; i < 4; i++)
#pragma unroll
        for (int j = 0; j < 8; j++)
#pragma unroll
            for (int v = 0; v < 4; v++) acc[i][j][v] = 0.0f;

#define PREFETCH(st, k0)                                                          \
    do {                                                                          \
        __nv_bfloat16* aH = sm + (st) * STG;                                      \
        __nv_bfloat16* aL = aH + ASZ;                                             \
        __nv_bfloat16* bH = aL + ASZ;                                             \
        __nv_bfloat16* bL = bH + BSZ;                                             \
        const __nv_bfloat16* gah = Ah + (size_t)(m0 + tid) * K + (k0);            \
        const __nv_bfloat16* gal = Al + (size_t)(m0 + tid) * K + (k0);            \
        _Pragma("unroll")                                                         \
        for (int cchunk = 0; cchunk < 4; cchunk++) {                              \
            cpasync16(aH + tid * A_STRIDE + cchunk * 8, gah + cchunk * 8);        \
            cpasync16(aL + tid * A_STRIDE + cchunk * 8, gal + cchunk * 8);        \
        }                                                                         \
        cpasync16(bH + br0 * B_STRIDE + bc0, Bh + (size_t)((k0) + br0) * N + n0 + bc0); \
        cpasync16(bH + br1 * B_STRIDE + bc0, Bh + (size_t)((k0) + br1) * N + n0 + bc0); \
        cpasync16(bL + br0 * B_STRIDE + bc0, Bl + (size_t)((k0) + br0) * N + n0 + bc0); \
        cpasync16(bL + br1 * B_STRIDE + bc0, Bl + (size_t)((k0) + br1) * N + n0 + bc0); \
    } while (0)

    const int nk = K / BK;
    PREFETCH(0, 0);
    CP_COMMIT();

    const int lrow = lane & 15;
    const int lcol = (lane >> 4) * 8;

    for (int i = 0; i < nk; i++) {
        if (i + 1 < nk) PREFETCH((i + 1) & 1, (i + 1) * BK);
        CP_COMMIT();
        CP_WAIT1();
        __syncthreads();

        const int st = i & 1;
        __nv_bfloat16* aH = sm + st * STG;
        __nv_bfloat16* aL = aH + ASZ;
        __nv_bfloat16* bH = aL + ASZ;
        __nv_bfloat16* bL = bH + BSZ;

#pragma unroll
        for (int kk = 0; kk < BK; kk += 16) {
            uint32_t ah[4][4], al[4][4];
#pragma unroll
            for (int mt = 0; mt < 4; mt++) {
                ldmx4(ah[mt], aH + (wm + mt * 16 + lrow) * A_STRIDE + kk + lcol);
                ldmx4(al[mt], aL + (wm + mt * 16 + lrow) * A_STRIDE + kk + lcol);
            }
#pragma unroll
            for (int ntp = 0; ntp < 4; ntp++) {
                uint32_t bh[4], bl[4];
                ldmx4t(bh, bH + (kk + lrow) * B_STRIDE + wn + ntp * 16 + lcol);
                ldmx4t(bl, bL + (kk + lrow) * B_STRIDE + wn + ntp * 16 + lcol);
#pragma unroll
                for (int mt = 0; mt < 4; mt++) {
                    float* a0 = acc[mt][2 * ntp];
                    float* a1 = acc[mt][2 * ntp + 1];
                    mma16816(a0, ah[mt], bh[0], bh[1]);
                    mma16816(a0, ah[mt], bl[0], bl[1]);
                    mma16816(a0, al[mt], bh[0], bh[1]);
                    mma16816(a1, ah[mt], bh[2], bh[3]);
                    mma16816(a1, ah[mt], bl[2], bl[3]);
                    mma16816(a1, al[mt], bh[2], bh[3]);
                }
            }
        }
        __syncthreads();
    }
#undef PREFETCH

    const int er = lane >> 2;
    const int ec = (lane & 3) * 2;
#pragma unroll
    for (int mt = 0; mt < 4; mt++)
#pragma unroll
        for (int nt = 0; nt < 8; nt++) {
            int r0 = m0 + wm + mt * 16 + er;
            int c0 = n0 + wn + nt * 8 + ec;
            float b0 = bias[c0], b1 = bias[c0 + 1];
            float v0 = acc[mt][nt][0] + b0, v1 = acc[mt][nt][1] + b1;
            float v2 = acc[mt][nt][2] + b0, v3 = acc[mt][nt][3] + b1;
            if (C) {
                *(float2*)(C + (size_t)r0 * N + c0) = make_float2(v0, v1);
                *(float2*)(C + (size_t)(r0 + 8) * N + c0) = make_float2(v2, v3);
            } else {
                __nv_bfloat16 h0 = __float2bfloat16(v0), h1 = __float2bfloat16(v1);
                __nv_bfloat16 h2 = __float2bfloat16(v2), h3 = __float2bfloat16(v3);
                *(__nv_bfloat162*)(Ch + (size_t)r0 * N + c0) = __nv_bfloat162(h0, h1);
                *(__nv_bfloat162*)(Ch + (size_t)(r0 + 8) * N + c0) = __nv_bfloat162(h2, h3);
                *(__nv_bfloat162*)(Cl + (size_t)r0 * N + c0) =
                    __nv_bfloat162(__float2bfloat16(v0 - __bfloat162float(h0)),
                                   __float2bfloat16(v1 - __bfloat162float(h1)));
                *(__nv_bfloat162*)(Cl + (size_t)(r0 + 8) * N + c0) =
                    __nv_bfloat162(__float2bfloat16(v2 - __bfloat162float(h2)),
                                   __float2bfloat16(v3 - __bfloat162float(h3)));
            }
        }
}

// ---------------------------------------------------------------------------
// Fused QKV GEMM: 384 CTAs (Q:256, K:64, V:64). V emits split bf16.
// ---------------------------------------------------------------------------
struct QKVArgs {
    const __nv_bfloat16 *xh, *xl, *yh, *yl;
    const __nv_bfloat16 *Wqh, *Wql, *Wkh, *Wkl, *Wvh, *Wvl;
    const float *bq, *bk, *bv;
    float *Q, *K;
    __nv_bfloat16 *Vh, *Vl;
};

__global__ __launch_bounds__(256) void qkv_gemm_kernel(QKVArgs a)
{
    extern __shared__ __nv_bfloat16 sm[];
    int bid = blockIdx.x;
    if (bid < 256) {
        gemm_tile(a.xh, a.xl, a.Wqh, a.Wql, a.bq,
                  a.Q, nullptr, nullptr,
                  D_MODEL, D_MODEL, (bid >> 5) * BM, (bid & 31) * BN, sm);
    } else if (bid < 320) {
        int t = bid - 256;
        gemm_tile(a.yh, a.yl, a.Wkh, a.Wkl, a.bk,
                  a.K, nullptr, nullptr,
                  GS_DIM, D_MODEL, (t >> 3) * BM, (t & 7) * BN, sm);
    } else {
        int t = bid - 320;
        gemm_tile(a.yh, a.yl, a.Wvh, a.Wvl, a.bv,
                  nullptr, a.Vh, a.Vl,
                  GS_DIM, D_MODEL, (t >> 3) * BM, (t & 7) * BN, sm);
    }
}

// Standalone GEMM (output projection), fp32 out
__global__ __launch_bounds__(256) void gemm_mma_kernel(
    const __nv_bfloat16* __restrict__ Ah, const __nv_bfloat16* __restrict__ Al,
    const __nv_bfloat16* __restrict__ Bh, const __nv_bfloat16* __restrict__ Bl,
    const float* __restrict__ bias, float* __restrict__ C, int N, int K)
{
    extern __shared__ __nv_bfloat16 sm[];
    gemm_tile(Ah, Al, Bh, Bl, bias, C, nullptr, nullptr,
              N, K, blockIdx.y * BM, blockIdx.x * BN, sm);
}

// ---------------------------------------------------------------------------
// RoPE: table, then one fused rotate+split launch covering Q and K
// ---------------------------------------------------------------------------
__global__ void rope_table_kernel()
{
    int idx = blockIdx.x * blockDim.x + threadIdx.x;
    if (idx >= S_LEN * GVS) return;
    int s = idx / GVS, i = idx % GVS;
    double phi = exp(-((double)i / (double)GVS) * log(5000.0));
    double sn, c;
    sincos((double)s * phi, &sn, &c);   // sin first, cos second
    g_tab[idx] = make_float2((float)c, (float)sn);
}

struct RopeArgs {
    const float *Q, *K;
    __nv_bfloat16 *Qh, *Ql, *Kh, *Kl;
};

__global__ void rope_split_kernel(RopeArgs a)
{
    const int qtot = S_LEN * N_HEAD * GVS;
    const int ktot = S_LEN * KV_HEAD * GVS;
    int idx = blockIdx.x * blockDim.x + threadIdx.x;
    if (idx >= qtot + ktot) return;

    const float* T; __nv_bfloat16 *hi, *lo;
    int H; float scale;
    if (idx < qtot) {
        T = a.Q; hi = a.Qh; lo = a.Ql; H = N_HEAD;
        scale = 0.08838834764831845f;
    } else {
        idx -= qtot;
        T = a.K; hi = a.Kh; lo = a.Kl; H = KV_HEAD;
        scale = 1.0f;
    }
    int i = idx % GVS;
    int h = (idx / GVS) % H;
    int s = idx / (GVS * H);
    float2 cs = g_tab[s * GVS + i];
    size_t base = ((size_t)s * H + h) * HEAD_DIM + 2 * i;
    float tr = T[base], ti = T[base + 1];
    float ro = (tr * cs.x - ti * cs.y) * scale;
    float io = (tr * cs.y + ti * cs.x) * scale;
    __nv_bfloat16 h0 = __float2bfloat16(ro);
    __nv_bfloat16 h1 = __float2bfloat16(io);
    hi[base]     = h0;
    hi[base + 1] = h1;
    lo[base]     = __float2bfloat16(ro - __bfloat162float(h0));
    lo[base + 1] = __float2bfloat16(io - __bfloat162float(h1));
}

// ---------------------------------------------------------------------------
// MMA flash attention (split bf16 in/out). Heavy q-tiles first.
// ---------------------------------------------------------------------------
#define QT 128
#define KT 64
#define DSTR 136
#define PSTR 72

__global__ __launch_bounds__(256) void attn_mma_kernel(
    const __nv_bfloat16* __restrict__ Qh, const __nv_bfloat16* __restrict__ Ql,
    const __nv_bfloat16* __restrict__ Kh, const __nv_bfloat16* __restrict__ Kl,
    const __nv_bfloat16* __restrict__ Vh, const __nv_bfloat16* __restrict__ Vl,
    __nv_bfloat16* __restrict__ Oh, __nv_bfloat16* __restrict__ Ol)
{
    extern __shared__ __nv_bfloat16 sb[];
    __nv_bfloat16* sQh = sb;
    __nv_bfloat16* sQl = sQh + QT * DSTR;
    __nv_bfloat16* sKh = sQl + QT * DSTR;
    __nv_bfloat16* sKl = sKh + KT * DSTR;
    __nv_bfloat16* sVh = sKl + KT * DSTR;
    __nv_bfloat16* sVl = sVh + KT * DSTR;
    __nv_bfloat16* sPh = sVl + KT * DSTR;
    __nv_bfloat16* sPl = sPh + QT * PSTR;

    const int tid  = threadIdx.x;
    const int lane = tid & 31;
    const int wid  = tid >> 5;
    const int wrow = wid * 16;
    const int qt   = (gridDim.x - 1) - blockIdx.x;
    const int h    = blockIdx.y;
    const int q0   = qt * QT;
    const int kvh  = h >> 2;

    for (int t = tid; t < QT * 16; t += 256) {
        int r = t >> 4, c8 = (t & 15) * 8;
        const uint4* ph = (const uint4*)(Qh + (size_t)(q0 + r) * D_MODEL + h * HEAD_DIM + c8);
        const uint4* pl = (const uint4*)(Ql + (size_t)(q0 + r) * D_MODEL + h * HEAD_DIM + c8);
        *(uint4*)(sQh + r * DSTR + c8) = *ph;
        *(uint4*)(sQl + r * DSTR + c8) = *pl;
    }

    float oacc[16][4];
#pragma unroll
    for (int nt = 0; nt < 16; nt++)
#pragma unroll
        for (int v = 0; v < 4; v++) oacc[nt][v] = 0.0f;
    float m_lo = -1e30f, m_hi = -1e30f, l_lo = 0.0f, l_hi = 0.0f;

    const int lrow = lane & 15;
    const int lcol = (lane >> 4) * 8;
    const int er   = lane >> 2;
    const int ec   = (lane & 3) * 2;

    const int ktmax = 2 * qt + 1;
    for (int kt = 0; kt <= ktmax; kt++) {
        const int k0 = kt * KT;
        __syncthreads();
        for (int t = tid; t < KT * 16; t += 256) {
            int r = t >> 4, c8 = (t & 15) * 8;
            size_t g = (size_t)(k0 + r) * GS_DIM + kvh * HEAD_DIM + c8;
            *(uint4*)(sKh + r * DSTR + c8) = *(const uint4*)(Kh + g);
            *(uint4*)(sKl + r * DSTR + c8) = *(const uint4*)(Kl + g);
            *(uint4*)(sVh + r * DSTR + c8) = *(const uint4*)(Vh + g);
            *(uint4*)(sVl + r * DSTR + c8) = *(const uint4*)(Vl + g);
        }
        __syncthreads();

        if (k0 > q0 + wrow + 15) continue;

        float sacc[8][4];
#pragma unroll
        for (int nt = 0; nt < 8; nt++)
#pragma unroll
            for (int v = 0; v < 4; v++) sacc[nt][v] = 0.0f;

#pragma unroll
        for (int kk = 0; kk < 8; kk++) {
            uint32_t ah[4], al[4];
            ldmx4(ah, sQh + (wrow + lrow) * DSTR + kk * 16 + lcol);
            ldmx4(al, sQl + (wrow + lrow) * DSTR + kk * 16 + lcol);
#pragma unroll
            for (int np = 0; np < 4; np++) {
                uint32_t bh[4], bl[4];
                ldmx4(bh, sKh + (np * 16 + lrow) * DSTR + kk * 16 + lcol);
                ldmx4(bl, sKl + (np * 16 + lrow) * DSTR + kk * 16 + lcol);
                mma16816(sacc[2 * np],     ah, bh[0], bh[2]);
                mma16816(sacc[2 * np],     ah, bl[0], bl[2]);
                mma16816(sacc[2 * np],     al, bh[0], bh[2]);
                mma16816(sacc[2 * np + 1], ah, bh[1], bh[3]);
                mma16816(sacc[2 * np + 1], ah, bl[1], bl[3]);
                mma16816(sacc[2 * np + 1], al, bh[1], bh[3]);
            }
        }

        if (kt >= 2 * qt) {
            int gq_lo = q0 + wrow + er;
            int gq_hi = gq_lo + 8;
#pragma unroll
            for (int nt = 0; nt < 8; nt++) {
                int c0 = k0 + nt * 8 + ec;
                if (c0 > gq_lo)     sacc[nt][0] = -1e30f;
                if (c0 + 1 > gq_lo) sacc[nt][1] = -1e30f;
                if (c0 > gq_hi)     sacc[nt][2] = -1e30f;
                if (c0 + 1 > gq_hi) sacc[nt][3] = -1e30f;
            }
        }

        float mx_lo = -1e30f, mx_hi = -1e30f;
#pragma unroll
        for (int nt = 0; nt < 8; nt++) {
            mx_lo = fmaxf(mx_lo, fmaxf(sacc[nt][0], sacc[nt][1]));
            mx_hi = fmaxf(mx_hi, fmaxf(sacc[nt][2], sacc[nt][3]));
        }
        mx_lo = fmaxf(mx_lo, __shfl_xor_sync(0xffffffffu, mx_lo, 1));
        mx_lo = fmaxf(mx_lo, __shfl_xor_sync(0xffffffffu, mx_lo, 2));
        mx_hi = fmaxf(mx_hi, __shfl_xor_sync(0xffffffffu, mx_hi, 1));
        mx_hi = fmaxf(mx_hi, __shfl_xor_sync(0xffffffffu, mx_hi, 2));

        float mn_lo = fmaxf(m_lo, mx_lo);
        float mn_hi = fmaxf(m_hi, mx_hi);
        float al_lo = __expf(m_lo - mn_lo);
        float al_hi = __expf(m_hi - mn_hi);

        float sum_lo = 0.0f, sum_hi = 0.0f;
#pragma unroll
        for (int nt = 0; nt < 8; nt++) {
            float p0 = __expf(sacc[nt][0] - mn_lo);
            float p1 = __expf(sacc[nt][1] - mn_lo);
            float p2 = __expf(sacc[nt][2] - mn_hi);
            float p3 = __expf(sacc[nt][3] - mn_hi);
            sum_lo += p0 + p1;
            sum_hi += p2 + p3;
            int c = nt * 8 + ec;
            __nv_bfloat16 h0 = __float2bfloat16(p0);
            __nv_bfloat16 h1 = __float2bfloat16(p1);
            __nv_bfloat16 h2 = __float2bfloat16(p2);
            __nv_bfloat16 h3 = __float2bfloat16(p3);
            sPh[(wrow + er) * PSTR + c]     = h0;
            sPh[(wrow + er) * PSTR + c + 1] = h1;
            sPh[(wrow + er + 8) * PSTR + c]     = h2;
            sPh[(wrow + er + 8) * PSTR + c + 1] = h3;
            sPl[(wrow + er) * PSTR + c]     = __float2bfloat16(p0 - __bfloat162float(h0));
            sPl[(wrow + er) * PSTR + c + 1] = __float2bfloat16(p1 - __bfloat162float(h1));
            sPl[(wrow + er + 8) * PSTR + c]     = __float2bfloat16(p2 - __bfloat162float(h2));
            sPl[(wrow + er + 8) * PSTR + c + 1] = __float2bfloat16(p3 - __bfloat162float(h3));
        }
        sum_lo += __shfl_xor_sync(0xffffffffu, sum_lo, 1);
        sum_lo += __shfl_xor_sync(0xffffffffu, sum_lo, 2);
        sum_hi += __shfl_xor_sync(0xffffffffu, sum_hi, 1);
        sum_hi += __shfl_xor_sync(0xffffffffu, sum_hi, 2);

        l_lo = l_lo * al_lo + sum_lo;
        l_hi = l_hi * al_hi + sum_hi;
        m_lo = mn_lo; m_hi = mn_hi;

#pragma unroll
        for (int nt = 0; nt < 16; nt++) {
            oacc[nt][0] *= al_lo; oacc[nt][1] *= al_lo;
            oacc[nt][2] *= al_hi; oacc[nt][3] *= al_hi;
        }
        __syncwarp();

#pragma unroll
        for (int kk = 0; kk < 4; kk++) {
            uint32_t ah[4], al2[4];
            ldmx4(ah,  sPh + (wrow + lrow) * PSTR + kk * 16 + lcol);
            ldmx4(al2, sPl + (wrow + lrow) * PSTR + kk * 16 + lcol);
#pragma unroll
            for (int np = 0; np < 8; np++) {
                uint32_t bh[4], bl[4];
                ldmx4t(bh, sVh + (kk * 16 + lrow) * DSTR + np * 16 + lcol);
                ldmx4t(bl, sVl + (kk * 16 + lrow) * DSTR + np * 16 + lcol);
                mma16816(oacc[2 * np],     ah,  bh[0], bh[1]);
                mma16816(oacc[2 * np],     al2, bh[0], bh[1]);
                mma16816(oacc[2 * np],     ah,  bl[0], bl[1]);
                mma16816(oacc[2 * np + 1], ah,  bh[2], bh[3]);
                mma16816(oacc[2 * np + 1], al2, bh[2], bh[3]);
                mma16816(oacc[2 * np + 1], ah,  bl[2], bl[3]);
            }
        }
    }

    float inv_lo = 1.0f / l_lo;
    float inv_hi = 1.0f / l_hi;
    int gq_lo = q0 + wrow + er;
#pragma unroll
    for (int nt = 0; nt < 16; nt++) {
        int c = h * HEAD_DIM + nt * 8 + ec;
        float v0 = oacc[nt][0] * inv_lo, v1 = oacc[nt][1] * inv_lo;
        float v2 = oacc[nt][2] * inv_hi, v3 = oacc[nt][3] * inv_hi;
        __nv_bfloat16 h0 = __float2bfloat16(v0), h1 = __float2bfloat16(v1);
        __nv_bfloat16 h2 = __float2bfloat16(v2), h3 = __float2bfloat16(v3);
        __nv_bfloat162* p;
        p = (__nv_bfloat162*)(Oh + (size_t)gq_lo * D_MODEL + c);
        *p = __nv_bfloat162(h0, h1);
        p = (__nv_bfloat162*)(Oh + (size_t)(gq_lo + 8) * D_MODEL + c);
        *p = __nv_bfloat162(h2, h3);
        p = (__nv_bfloat162*)(Ol + (size_t)gq_lo * D_MODEL + c);
        *p = __nv_bfloat162(__float2bfloat16(v0 - __bfloat162float(h0)),
                            __float2bfloat16(v1 - __bfloat162float(h1)));
        p = (__nv_bfloat162*)(Ol + (size_t)(gq_lo + 8) * D_MODEL + c);
        *p = __nv_bfloat162(__float2bfloat16(v2 - __bfloat162float(h2)),
                            __float2bfloat16(v3 - __bfloat162float(h3)));
    }
}

// ---------------------------------------------------------------------------
// Launch. Input order (R6-confirmed dict order):
//   0:x 1:y 2:Wq 3:bq 4:Wk 5:bk 6:Wv 7:bv 8:Wo 9:bo
// ---------------------------------------------------------------------------
extern "C" void kernel_launch(void* const* d_in, const int* in_sizes, int n_in,
                              void* d_out, int out_size)
{
    (void)in_sizes; (void)n_in; (void)out_size;
    const float* x  = (const float*)d_in[0];
    const float* y  = (const float*)d_in[1];
    const float* Wq = (const float*)d_in[2];
    const float* bq = (const float*)d_in[3];
    const float* Wk = (const float*)d_in[4];
    const float* bk = (const float*)d_in[5];
    const float* Wv = (const float*)d_in[6];
    const float* bv = (const float*)d_in[7];
    const float* Wo = (const float*)d_in[8];
    const float* bo = (const float*)d_in[9];
    float* out = (float*)d_out;

    float *Qb, *Kb;
    cudaGetSymbolAddress((void**)&Qb, g_Q);
    cudaGetSymbolAddress((void**)&Kb, g_K);

    __nv_bfloat16 *xh, *xl, *yh, *yl, *Wqh, *Wql, *Wkh, *Wkl, *Wvh, *Wvl,
                  *Woh, *Wol, *AOh, *AOl, *Qsh, *Qsl, *Ksh, *Ksl, *Vsh, *Vsl;
    cudaGetSymbolAddress((void**)&xh, g_xh);   cudaGetSymbolAddress((void**)&xl, g_xl);
    cudaGetSymbolAddress((void**)&yh, g_yh);   cudaGetSymbolAddress((void**)&yl, g_yl);
    cudaGetSymbolAddress((void**)&Wqh, g_Wqh); cudaGetSymbolAddress((void**)&Wql, g_Wql);
    cudaGetSymbolAddress((void**)&Wkh, g_Wkh); cudaGetSymbolAddress((void**)&Wkl, g_Wkl);
    cudaGetSymbolAddress((void**)&Wvh, g_Wvh); cudaGetSymbolAddress((void**)&Wvl, g_Wvl);
    cudaGetSymbolAddress((void**)&Woh, g_Woh); cudaGetSymbolAddress((void**)&Wol, g_Wol);
    cudaGetSymbolAddress((void**)&AOh, g_AOh); cudaGetSymbolAddress((void**)&AOl, g_AOl);
    cudaGetSymbolAddress((void**)&Qsh, g_Qh);  cudaGetSymbolAddress((void**)&Qsl, g_Ql);
    cudaGetSymbolAddress((void**)&Ksh, g_Kh);  cudaGetSymbolAddress((void**)&Ksl, g_Kl);
    cudaGetSymbolAddress((void**)&Vsh, g_Vh);  cudaGetSymbolAddress((void**)&Vsl, g_Vl);

    cudaFuncSetAttribute(qkv_gemm_kernel, cudaFuncAttributeMaxDynamicSharedMemorySize, GEMM_SMEM);
    cudaFuncSetAttribute(gemm_mma_kernel, cudaFuncAttributeMaxDynamicSharedMemorySize, GEMM_SMEM);
    const int smem_attn = (2 * QT * DSTR + 4 * KT * DSTR + 2 * QT * PSTR) * 2;
    cudaFuncSetAttribute(attn_mma_kernel, cudaFuncAttributeMaxDynamicSharedMemorySize, smem_attn);

    // RoPE table (independent)
    rope_table_kernel<<<(S_LEN * GVS + 255) / 256, 256>>>();

    // Mega-split: x, y, Wq, Wk, Wv, Wo in one launch
    {
        SplitArgs a;
        const float* srcs[6] = {x, y, Wq, Wk, Wv, Wo};
        __nv_bfloat16* his[6] = {xh, yh, Wqh, Wkh, Wvh, Woh};
        __nv_bfloat16* los[6] = {xl, yl, Wql, Wkl, Wvl, Wol};
        int ns[6] = {S_LEN * D_MODEL, S_LEN * D_MODEL,
                     D_MODEL * D_MODEL, D_MODEL * GS_DIM,
                     D_MODEL * GS_DIM, D_MODEL * D_MODEL};
        int acc = 0;
        for (int i = 0; i < 6; i++) {
            a.src[i] = srcs[i]; a.hi[i] = his[i]; a.lo[i] = los[i];
            a.off[i] = acc; acc += ns[i];
        }
        a.off[6] = acc;
        mega_split_kernel<<<(acc + 255) / 256, 256>>>(a);
    }

    // Fused QKV projection (384 CTAs; V emits split bf16 directly)
    {
        QKVArgs a;
        a.xh = xh; a.xl = xl; a.yh = yh; a.yl = yl;
        a.Wqh = Wqh; a.Wql = Wql; a.Wkh = Wkh; a.Wkl = Wkl; a.Wvh = Wvh; a.Wvl = Wvl;
        a.bq = bq; a.bk = bk; a.bv = bv;
        a.Q = Qb; a.K = Kb; a.Vh = Vsh; a.Vl = Vsl;
        qkv_gemm_kernel<<<384, 256, GEMM_SMEM>>>(a);
    }

    // Fused RoPE + split for Q and K (one launch)
    {
        RopeArgs a;
        a.Q = Qb; a.K = Kb;
        a.Qh = Qsh; a.Ql = Qsl; a.Kh = Ksh; a.Kl = Ksl;
        int tot = S_LEN * (N_HEAD + KV_HEAD) * GVS;
        rope_split_kernel<<<(tot + 255) / 256, 256>>>(a);
    }

    // MMA flash attention -> split bf16 AO
    attn_mma_kernel<<<dim3(S_LEN / QT, N_HEAD), 256, smem_attn>>>(
        Qsh, Qsl, Ksh, Ksl, Vsh, Vsl, AOh, AOl);

    // Output projection
    gemm_mma_kernel<<<dim3(D_MODEL / BN, S_LEN / BM), 256, GEMM_SMEM>>>(
        AOh, AOl, Woh, Wol, bo, out, D_MODEL, D_MODEL);
}

// round 14
// speedup vs baseline: 1.0003x; 1.0003x over previous
#include <cuda_runtime.h>
#include <cuda_bf16.h>
#include <math.h>
#include <stdint.h>

// ---------------------------------------------------------------------------
// Problem constants (B=1, S=2048, D=4096, n_head=32, kv_head=8, hd=128)
// ---------------------------------------------------------------------------
#define S_LEN 2048
#define D_MODEL 4096
#define GS_DIM 1024
#define N_HEAD 32
#define KV_HEAD 8
#define HEAD_DIM 128
#define GVS 64

// fp32 scratch
__device__ float g_Q[S_LEN * D_MODEL];
__device__ float g_K[S_LEN * GS_DIM];
__device__ float2 g_tab[S_LEN * GVS];

// bf16 hi/lo splits
__device__ __nv_bfloat16 g_xh[S_LEN * D_MODEL],  g_xl[S_LEN * D_MODEL];
__device__ __nv_bfloat16 g_yh[S_LEN * D_MODEL],  g_yl[S_LEN * D_MODEL];
__device__ __nv_bfloat16 g_Wqh[D_MODEL * D_MODEL], g_Wql[D_MODEL * D_MODEL];
__device__ __nv_bfloat16 g_Wkh[D_MODEL * GS_DIM],  g_Wkl[D_MODEL * GS_DIM];
__device__ __nv_bfloat16 g_Wvh[D_MODEL * GS_DIM],  g_Wvl[D_MODEL * GS_DIM];
__device__ __nv_bfloat16 g_Woh[D_MODEL * D_MODEL], g_Wol[D_MODEL * D_MODEL];
__device__ __nv_bfloat16 g_AOh[S_LEN * D_MODEL],   g_AOl[S_LEN * D_MODEL];
__device__ __nv_bfloat16 g_Qh[S_LEN * D_MODEL],    g_Ql[S_LEN * D_MODEL];
__device__ __nv_bfloat16 g_Kh[S_LEN * GS_DIM],     g_Kl[S_LEN * GS_DIM];
__device__ __nv_bfloat16 g_Vh[S_LEN * GS_DIM],     g_Vl[S_LEN * GS_DIM];

// ---------------------------------------------------------------------------
// Mega-split: all 6 fp32->bf16 hi/lo conversions in one launch
// ---------------------------------------------------------------------------
struct SplitArgs {
    const float* src[6];
    __nv_bfloat16* hi[6];
    __nv_bfloat16* lo[6];
    int off[7];
};

__global__ void mega_split_kernel(SplitArgs a)
{
    int i = blockIdx.x * blockDim.x + threadIdx.x;
    if (i >= a.off[6]) return;
    int s = 0;
#pragma unroll
    for (int t = 1; t < 6; t++) s += (i >= a.off[t]);
    int j = i - a.off[s];
    float v = a.src[s][j];
    __nv_bfloat16 h = __float2bfloat16(v);
    a.hi[s][j] = h;
    a.lo[s][j] = __float2bfloat16(v - __bfloat162float(h));
}

// ---------------------------------------------------------------------------
// MMA helpers
// ---------------------------------------------------------------------------
__device__ __forceinline__ void ldmx4(uint32_t* r, const void* p)
{
    uint32_t a = (uint32_t)__cvta_generic_to_shared(p);
    asm volatile("ldmatrix.sync.aligned.m8n8.x4.shared.b16 {%0,%1,%2,%3}, [%4];"
                 : "=r"(r[0]), "=r"(r[1]), "=r"(r[2]), "=r"(r[3]) : "r"(a));
}
__device__ __forceinline__ void ldmx4t(uint32_t* r, const void* p)
{
    uint32_t a = (uint32_t)__cvta_generic_to_shared(p);
    asm volatile("ldmatrix.sync.aligned.m8n8.x4.trans.shared.b16 {%0,%1,%2,%3}, [%4];"
                 : "=r"(r[0]), "=r"(r[1]), "=r"(r[2]), "=r"(r[3]) : "r"(a));
}
__device__ __forceinline__ void mma16816(float* d, const uint32_t* a,
                                         uint32_t b0, uint32_t b1)
{
    asm volatile(
        "mma.sync.aligned.m16n8k16.row.col.f32.bf16.bf16.f32 "
        "{%0,%1,%2,%3}, {%4,%5,%6,%7}, {%8,%9}, {%0,%1,%2,%3};"
        : "+f"(d[0]), "+f"(d[1]), "+f"(d[2]), "+f"(d[3])
        : "r"(a[0]), "r"(a[1]), "r"(a[2]), "r"(a[3]), "r"(b0), "r"(b1));
}
__device__ __forceinline__ void cpasync16(void* smem, const void* gmem)
{
    uint32_t a = (uint32_t)__cvta_generic_to_shared(smem);
    asm volatile("cp.async.cg.shared.global [%0], [%1], 16;" :: "r"(a), "l"(gmem));
}
#define CP_COMMIT() asm volatile("cp.async.commit_group;")
#define CP_WAIT1()  asm volatile("cp.async.wait_group 1;")

// ---------------------------------------------------------------------------
// Split-bf16 3-pass GEMM tile: CTA 256x128, BK=32, 8 warps of 64x64.
// Double-buffered cp.async. Output fp32 (C) or split bf16 (Ch/Cl if C==null).
// ---------------------------------------------------------------------------
#define BM 256
#define BN 128
#define BK 32
#define A_STRIDE 40
#define B_STRIDE 136
#define ASZ (BM * A_STRIDE)
#define BSZ (BK * B_STRIDE)
#define STG (2 * ASZ + 2 * BSZ)
#define GEMM_SMEM (2 * STG * 2)   // bytes (~117 KB)

__device__ __forceinline__ void gemm_tile(
    const __nv_bfloat16* __restrict__ Ah, const __nv_bfloat16* __restrict__ Al,
    const __nv_bfloat16* __restrict__ Bh, const __nv_bfloat16* __restrict__ Bl,
    const float* __restrict__ bias,
    float* __restrict__ C, __nv_bfloat16* __restrict__ Ch,
    __nv_bfloat16* __restrict__ Cl,
    int N, int K, int m0, int n0, __nv_bfloat16* sm)
{
    const int tid  = threadIdx.x;
    const int lane = tid & 31;
    const int wid  = tid >> 5;
    const int wm   = (wid >> 1) * 64;    // 0,64,128,192
    const int wn   = (wid & 1) * 64;     // 0,64

    // A staging: thread tid loads row tid, 4 chunks of 8 (cols 0,8,16,24)
    // B staging: 512 chunks, 2 per thread (rows 0..15 and 16..31)
    const int br0 = tid >> 4, bc0 = (tid & 15) * 8;
    const int br1 = br0 + 16;

    float acc[4][8][4];
#pragma unroll
    for (int i = 0; i < 4; i++)
#pragma unroll
        for (int j = 0; j < 8; j++)
#pragma unroll
            for (int v = 0; v < 4; v++) acc[i][j][v] = 0.0f;

#define PREFETCH(st, k0)                                                          \
    do {                                                                          \
        __nv_bfloat16* aH = sm + (st) * STG;                                      \
        __nv_bfloat16* aL = aH + ASZ;                                             \
        __nv_bfloat16* bH = aL + ASZ;                                             \
        __nv_bfloat16* bL = bH + BSZ;                                             \
        const __nv_bfloat16* gah = Ah + (size_t)(m0 + tid) * K + (k0);            \
        const __nv_bfloat16* gal = Al + (size_t)(m0 + tid) * K + (k0);            \
        _Pragma("unroll")                                                         \
        for (int cchunk = 0; cchunk < 4; cchunk++) {                              \
            cpasync16(aH + tid * A_STRIDE + cchunk * 8, gah + cchunk * 8);        \
            cpasync16(aL + tid * A_STRIDE + cchunk * 8, gal + cchunk * 8);        \
        }                                                                         \
        cpasync16(bH + br0 * B_STRIDE + bc0, Bh + (size_t)((k0) + br0) * N + n0 + bc0); \
        cpasync16(bH + br1 * B_STRIDE + bc0, Bh + (size_t)((k0) + br1) * N + n0 + bc0); \
        cpasync16(bL + br0 * B_STRIDE + bc0, Bl + (size_t)((k0) + br0) * N + n0 + bc0); \
        cpasync16(bL + br1 * B_STRIDE + bc0, Bl + (size_t)((k0) + br1) * N + n0 + bc0); \
    } while (0)

    const int nk = K / BK;
    PREFETCH(0, 0);
    CP_COMMIT();

    const int lrow = lane & 15;
    const int lcol = (lane >> 4) * 8;

    for (int i = 0; i < nk; i++) {
        if (i + 1 < nk) PREFETCH((i + 1) & 1, (i + 1) * BK);
        CP_COMMIT();
        CP_WAIT1();
        __syncthreads();

        const int st = i & 1;
        __nv_bfloat16* aH = sm + st * STG;
        __nv_bfloat16* aL = aH + ASZ;
        __nv_bfloat16* bH = aL + ASZ;
        __nv_bfloat16* bL = bH + BSZ;

#pragma unroll
        for (int kk = 0; kk < BK; kk += 16) {
            uint32_t ah[4][4], al[4][4];
#pragma unroll
            for (int mt = 0; mt < 4; mt++) {
                ldmx4(ah[mt], aH + (wm + mt * 16 + lrow) * A_STRIDE + kk + lcol);
                ldmx4(al[mt], aL + (wm + mt * 16 + lrow) * A_STRIDE + kk + lcol);
            }
#pragma unroll
            for (int ntp = 0; ntp < 4; ntp++) {
                uint32_t bh[4], bl[4];
                ldmx4t(bh, bH + (kk + lrow) * B_STRIDE + wn + ntp * 16 + lcol);
                ldmx4t(bl, bL + (kk + lrow) * B_STRIDE + wn + ntp * 16 + lcol);
#pragma unroll
                for (int mt = 0; mt < 4; mt++) {
                    float* a0 = acc[mt][2 * ntp];
                    float* a1 = acc[mt][2 * ntp + 1];
                    mma16816(a0, ah[mt], bh[0], bh[1]);
                    mma16816(a0, ah[mt], bl[0], bl[1]);
                    mma16816(a0, al[mt], bh[0], bh[1]);
                    mma16816(a1, ah[mt], bh[2], bh[3]);
                    mma16816(a1, ah[mt], bl[2], bl[3]);
                    mma16816(a1, al[mt], bh[2], bh[3]);
                }
            }
        }
        __syncthreads();
    }
#undef PREFETCH

    const int er = lane >> 2;
    const int ec = (lane & 3) * 2;
#pragma unroll
    for (int mt = 0; mt < 4; mt++)
#pragma unroll
        for (int nt = 0; nt < 8; nt++) {
            int r0 = m0 + wm + mt * 16 + er;
            int c0 = n0 + wn + nt * 8 + ec;
            float b0 = bias[c0], b1 = bias[c0 + 1];
            float v0 = acc[mt][nt][0] + b0, v1 = acc[mt][nt][1] + b1;
            float v2 = acc[mt][nt][2] + b0, v3 = acc[mt][nt][3] + b1;
            if (C) {
                *(float2*)(C + (size_t)r0 * N + c0) = make_float2(v0, v1);
                *(float2*)(C + (size_t)(r0 + 8) * N + c0) = make_float2(v2, v3);
            } else {
                __nv_bfloat16 h0 = __float2bfloat16(v0), h1 = __float2bfloat16(v1);
                __nv_bfloat16 h2 = __float2bfloat16(v2), h3 = __float2bfloat16(v3);
                *(__nv_bfloat162*)(Ch + (size_t)r0 * N + c0) = __nv_bfloat162(h0, h1);
                *(__nv_bfloat162*)(Ch + (size_t)(r0 + 8) * N + c0) = __nv_bfloat162(h2, h3);
                *(__nv_bfloat162*)(Cl + (size_t)r0 * N + c0) =
                    __nv_bfloat162(__float2bfloat16(v0 - __bfloat162float(h0)),
                                   __float2bfloat16(v1 - __bfloat162float(h1)));
                *(__nv_bfloat162*)(Cl + (size_t)(r0 + 8) * N + c0) =
                    __nv_bfloat162(__float2bfloat16(v2 - __bfloat162float(h2)),
                                   __float2bfloat16(v3 - __bfloat162float(h3)));
            }
        }
}

// ---------------------------------------------------------------------------
// Fused QKV GEMM: 384 CTAs (Q:256, K:64, V:64). V emits split bf16.
// ---------------------------------------------------------------------------
struct QKVArgs {
    const __nv_bfloat16 *xh, *xl, *yh, *yl;
    const __nv_bfloat16 *Wqh, *Wql, *Wkh, *Wkl, *Wvh, *Wvl;
    const float *bq, *bk, *bv;
    float *Q, *K;
    __nv_bfloat16 *Vh, *Vl;
};

__global__ __launch_bounds__(256) void qkv_gemm_kernel(QKVArgs a)
{
    extern __shared__ __nv_bfloat16 sm[];
    int bid = blockIdx.x;
    if (bid < 256) {
        gemm_tile(a.xh, a.xl, a.Wqh, a.Wql, a.bq,
                  a.Q, nullptr, nullptr,
                  D_MODEL, D_MODEL, (bid >> 5) * BM, (bid & 31) * BN, sm);
    } else if (bid < 320) {
        int t = bid - 256;
        gemm_tile(a.yh, a.yl, a.Wkh, a.Wkl, a.bk,
                  a.K, nullptr, nullptr,
                  GS_DIM, D_MODEL, (t >> 3) * BM, (t & 7) * BN, sm);
    } else {
        int t = bid - 320;
        gemm_tile(a.yh, a.yl, a.Wvh, a.Wvl, a.bv,
                  nullptr, a.Vh, a.Vl,
                  GS_DIM, D_MODEL, (t >> 3) * BM, (t & 7) * BN, sm);
    }
}

// Standalone GEMM (output projection), fp32 out
__global__ __launch_bounds__(256) void gemm_mma_kernel(
    const __nv_bfloat16* __restrict__ Ah, const __nv_bfloat16* __restrict__ Al,
    const __nv_bfloat16* __restrict__ Bh, const __nv_bfloat16* __restrict__ Bl,
    const float* __restrict__ bias, float* __restrict__ C, int N, int K)
{
    extern __shared__ __nv_bfloat16 sm[];
    gemm_tile(Ah, Al, Bh, Bl, bias, C, nullptr, nullptr,
              N, K, blockIdx.y * BM, blockIdx.x * BN, sm);
}

// ---------------------------------------------------------------------------
// RoPE: table, then one fused rotate+split launch covering Q and K
// ---------------------------------------------------------------------------
__global__ void rope_table_kernel()
{
    int idx = blockIdx.x * blockDim.x + threadIdx.x;
    if (idx >= S_LEN * GVS) return;
    int s = idx / GVS, i = idx % GVS;
    double phi = exp(-((double)i / (double)GVS) * log(5000.0));
    double sn, c;
    sincos((double)s * phi, &sn, &c);   // sin first, cos second
    g_tab[idx] = make_float2((float)c, (float)sn);
}

struct RopeArgs {
    const float *Q, *K;
    __nv_bfloat16 *Qh, *Ql, *Kh, *Kl;
};

__global__ void rope_split_kernel(RopeArgs a)
{
    const int qtot = S_LEN * N_HEAD * GVS;
    const int ktot = S_LEN * KV_HEAD * GVS;
    int idx = blockIdx.x * blockDim.x + threadIdx.x;
    if (idx >= qtot + ktot) return;

    const float* T; __nv_bfloat16 *hi, *lo;
    int H; float scale;
    if (idx < qtot) {
        T = a.Q; hi = a.Qh; lo = a.Ql; H = N_HEAD;
        scale = 0.08838834764831845f;
    } else {
        idx -= qtot;
        T = a.K; hi = a.Kh; lo = a.Kl; H = KV_HEAD;
        scale = 1.0f;
    }
    int i = idx % GVS;
    int h = (idx / GVS) % H;
    int s = idx / (GVS * H);
    float2 cs = g_tab[s * GVS + i];
    size_t base = ((size_t)s * H + h) * HEAD_DIM + 2 * i;
    float tr = T[base], ti = T[base + 1];
    float ro = (tr * cs.x - ti * cs.y) * scale;
    float io = (tr * cs.y + ti * cs.x) * scale;
    __nv_bfloat16 h0 = __float2bfloat16(ro);
    __nv_bfloat16 h1 = __float2bfloat16(io);
    hi[base]     = h0;
    hi[base + 1] = h1;
    lo[base]     = __float2bfloat16(ro - __bfloat162float(h0));
    lo[base + 1] = __float2bfloat16(io - __bfloat162float(h1));
}

// ---------------------------------------------------------------------------
// MMA flash attention (split bf16 in/out). Heavy q-tiles first.
// ---------------------------------------------------------------------------
#define QT 128
#define KT 64
#define DSTR 136
#define PSTR 72

__global__ __launch_bounds__(256) void attn_mma_kernel(
    const __nv_bfloat16* __restrict__ Qh, const __nv_bfloat16* __restrict__ Ql,
    const __nv_bfloat16* __restrict__ Kh, const __nv_bfloat16* __restrict__ Kl,
    const __nv_bfloat16* __restrict__ Vh, const __nv_bfloat16* __restrict__ Vl,
    __nv_bfloat16* __restrict__ Oh, __nv_bfloat16* __restrict__ Ol)
{
    extern __shared__ __nv_bfloat16 sb[];
    __nv_bfloat16* sQh = sb;
    __nv_bfloat16* sQl = sQh + QT * DSTR;
    __nv_bfloat16* sKh = sQl + QT * DSTR;
    __nv_bfloat16* sKl = sKh + KT * DSTR;
    __nv_bfloat16* sVh = sKl + KT * DSTR;
    __nv_bfloat16* sVl = sVh + KT * DSTR;
    __nv_bfloat16* sPh = sVl + KT * DSTR;
    __nv_bfloat16* sPl = sPh + QT * PSTR;

    const int tid  = threadIdx.x;
    const int lane = tid & 31;
    const int wid  = tid >> 5;
    const int wrow = wid * 16;
    const int qt   = (gridDim.x - 1) - blockIdx.x;
    const int h    = blockIdx.y;
    const int q0   = qt * QT;
    const int kvh  = h >> 2;

    for (int t = tid; t < QT * 16; t += 256) {
        int r = t >> 4, c8 = (t & 15) * 8;
        const uint4* ph = (const uint4*)(Qh + (size_t)(q0 + r) * D_MODEL + h * HEAD_DIM + c8);
        const uint4* pl = (const uint4*)(Ql + (size_t)(q0 + r) * D_MODEL + h * HEAD_DIM + c8);
        *(uint4*)(sQh + r * DSTR + c8) = *ph;
        *(uint4*)(sQl + r * DSTR + c8) = *pl;
    }

    float oacc[16][4];
#pragma unroll
    for (int nt = 0; nt < 16; nt++)
#pragma unroll
        for (int v = 0; v < 4; v++) oacc[nt][v] = 0.0f;
    float m_lo = -1e30f, m_hi = -1e30f, l_lo = 0.0f, l_hi = 0.0f;

    const int lrow = lane & 15;
    const int lcol = (lane >> 4) * 8;
    const int er   = lane >> 2;
    const int ec   = (lane & 3) * 2;

    const int ktmax = 2 * qt + 1;
    for (int kt = 0; kt <= ktmax; kt++) {
        const int k0 = kt * KT;
        __syncthreads();
        for (int t = tid; t < KT * 16; t += 256) {
            int r = t >> 4, c8 = (t & 15) * 8;
            size_t g = (size_t)(k0 + r) * GS_DIM + kvh * HEAD_DIM + c8;
            *(uint4*)(sKh + r * DSTR + c8) = *(const uint4*)(Kh + g);
            *(uint4*)(sKl + r * DSTR + c8) = *(const uint4*)(Kl + g);
            *(uint4*)(sVh + r * DSTR + c8) = *(const uint4*)(Vh + g);
            *(uint4*)(sVl + r * DSTR + c8) = *(const uint4*)(Vl + g);
        }
        __syncthreads();

        if (k0 > q0 + wrow + 15) continue;

        float sacc[8][4];
#pragma unroll
        for (int nt = 0; nt < 8; nt++)
#pragma unroll
            for (int v = 0; v < 4; v++) sacc[nt][v] = 0.0f;

#pragma unroll
        for (int kk = 0; kk < 8; kk++) {
            uint32_t ah[4], al[4];
            ldmx4(ah, sQh + (wrow + lrow) * DSTR + kk * 16 + lcol);
            ldmx4(al, sQl + (wrow + lrow) * DSTR + kk * 16 + lcol);
#pragma unroll
            for (int np = 0; np < 4; np++) {
                uint32_t bh[4], bl[4];
                ldmx4(bh, sKh + (np * 16 + lrow) * DSTR + kk * 16 + lcol);
                ldmx4(bl, sKl + (np * 16 + lrow) * DSTR + kk * 16 + lcol);
                mma16816(sacc[2 * np],     ah, bh[0], bh[2]);
                mma16816(sacc[2 * np],     ah, bl[0], bl[2]);
                mma16816(sacc[2 * np],     al, bh[0], bh[2]);
                mma16816(sacc[2 * np + 1], ah, bh[1], bh[3]);
                mma16816(sacc[2 * np + 1], ah, bl[1], bl[3]);
                mma16816(sacc[2 * np + 1], al, bh[1], bh[3]);
            }
        }

        if (kt >= 2 * qt) {
            int gq_lo = q0 + wrow + er;
            int gq_hi = gq_lo + 8;
#pragma unroll
            for (int nt = 0; nt < 8; nt++) {
                int c0 = k0 + nt * 8 + ec;
                if (c0 > gq_lo)     sacc[nt][0] = -1e30f;
                if (c0 + 1 > gq_lo) sacc[nt][1] = -1e30f;
                if (c0 > gq_hi)     sacc[nt][2] = -1e30f;
                if (c0 + 1 > gq_hi) sacc[nt][3] = -1e30f;
            }
        }

        float mx_lo = -1e30f, mx_hi = -1e30f;
#pragma unroll
        for (int nt = 0; nt < 8; nt++) {
            mx_lo = fmaxf(mx_lo, fmaxf(sacc[nt][0], sacc[nt][1]));
            mx_hi = fmaxf(mx_hi, fmaxf(sacc[nt][2], sacc[nt][3]));
        }
        mx_lo = fmaxf(mx_lo, __shfl_xor_sync(0xffffffffu, mx_lo, 1));
        mx_lo = fmaxf(mx_lo, __shfl_xor_sync(0xffffffffu, mx_lo, 2));
        mx_hi = fmaxf(mx_hi, __shfl_xor_sync(0xffffffffu, mx_hi, 1));
        mx_hi = fmaxf(mx_hi, __shfl_xor_sync(0xffffffffu, mx_hi, 2));

        float mn_lo = fmaxf(m_lo, mx_lo);
        float mn_hi = fmaxf(m_hi, mx_hi);
        float al_lo = __expf(m_lo - mn_lo);
        float al_hi = __expf(m_hi - mn_hi);

        float sum_lo = 0.0f, sum_hi = 0.0f;
#pragma unroll
        for (int nt = 0; nt < 8; nt++) {
            float p0 = __expf(sacc[nt][0] - mn_lo);
            float p1 = __expf(sacc[nt][1] - mn_lo);
            float p2 = __expf(sacc[nt][2] - mn_hi);
            float p3 = __expf(sacc[nt][3] - mn_hi);
            sum_lo += p0 + p1;
            sum_hi += p2 + p3;
            int c = nt * 8 + ec;
            __nv_bfloat16 h0 = __float2bfloat16(p0);
            __nv_bfloat16 h1 = __float2bfloat16(p1);
            __nv_bfloat16 h2 = __float2bfloat16(p2);
            __nv_bfloat16 h3 = __float2bfloat16(p3);
            sPh[(wrow + er) * PSTR + c]     = h0;
            sPh[(wrow + er) * PSTR + c + 1] = h1;
            sPh[(wrow + er + 8) * PSTR + c]     = h2;
            sPh[(wrow + er + 8) * PSTR + c + 1] = h3;
            sPl[(wrow + er) * PSTR + c]     = __float2bfloat16(p0 - __bfloat162float(h0));
            sPl[(wrow + er) * PSTR + c + 1] = __float2bfloat16(p1 - __bfloat162float(h1));
            sPl[(wrow + er + 8) * PSTR + c]     = __float2bfloat16(p2 - __bfloat162float(h2));
            sPl[(wrow + er + 8) * PSTR + c + 1] = __float2bfloat16(p3 - __bfloat162float(h3));
        }
        sum_lo += __shfl_xor_sync(0xffffffffu, sum_lo, 1);
        sum_lo += __shfl_xor_sync(0xffffffffu, sum_lo, 2);
        sum_hi += __shfl_xor_sync(0xffffffffu, sum_hi, 1);
        sum_hi += __shfl_xor_sync(0xffffffffu, sum_hi, 2);

        l_lo = l_lo * al_lo + sum_lo;
        l_hi = l_hi * al_hi + sum_hi;
        m_lo = mn_lo; m_hi = mn_hi;

#pragma unroll
        for (int nt = 0; nt < 16; nt++) {
            oacc[nt][0] *= al_lo; oacc[nt][1] *= al_lo;
            oacc[nt][2] *= al_hi; oacc[nt][3] *= al_hi;
        }
        __syncwarp();

#pragma unroll
        for (int kk = 0; kk < 4; kk++) {
            uint32_t ah[4], al2[4];
            ldmx4(ah,  sPh + (wrow + lrow) * PSTR + kk * 16 + lcol);
            ldmx4(al2, sPl + (wrow + lrow) * PSTR + kk * 16 + lcol);
#pragma unroll
            for (int np = 0; np < 8; np++) {
                uint32_t bh[4], bl[4];
                ldmx4t(bh, sVh + (kk * 16 + lrow) * DSTR + np * 16 + lcol);
                ldmx4t(bl, sVl + (kk * 16 + lrow) * DSTR + np * 16 + lcol);
                mma16816(oacc[2 * np],     ah,  bh[0], bh[1]);
                mma16816(oacc[2 * np],     al2, bh[0], bh[1]);
                mma16816(oacc[2 * np],     ah,  bl[0], bl[1]);
                mma16816(oacc[2 * np + 1], ah,  bh[2], bh[3]);
                mma16816(oacc[2 * np + 1], al2, bh[2], bh[3]);
                mma16816(oacc[2 * np + 1], ah,  bl[2], bl[3]);
            }
        }
    }

    float inv_lo = 1.0f / l_lo;
    float inv_hi = 1.0f / l_hi;
    int gq_lo = q0 + wrow + er;
#pragma unroll
    for (int nt = 0; nt < 16; nt++) {
        int c = h * HEAD_DIM + nt * 8 + ec;
        float v0 = oacc[nt][0] * inv_lo, v1 = oacc[nt][1] * inv_lo;
        float v2 = oacc[nt][2] * inv_hi, v3 = oacc[nt][3] * inv_hi;
        __nv_bfloat16 h0 = __float2bfloat16(v0), h1 = __float2bfloat16(v1);
        __nv_bfloat16 h2 = __float2bfloat16(v2), h3 = __float2bfloat16(v3);
        __nv_bfloat162* p;
        p = (__nv_bfloat162*)(Oh + (size_t)gq_lo * D_MODEL + c);
        *p = __nv_bfloat162(h0, h1);
        p = (__nv_bfloat162*)(Oh + (size_t)(gq_lo + 8) * D_MODEL + c);
        *p = __nv_bfloat162(h2, h3);
        p = (__nv_bfloat162*)(Ol + (size_t)gq_lo * D_MODEL + c);
        *p = __nv_bfloat162(__float2bfloat16(v0 - __bfloat162float(h0)),
                            __float2bfloat16(v1 - __bfloat162float(h1)));
        p = (__nv_bfloat162*)(Ol + (size_t)(gq_lo + 8) * D_MODEL + c);
        *p = __nv_bfloat162(__float2bfloat16(v2 - __bfloat162float(h2)),
                            __float2bfloat16(v3 - __bfloat162float(h3)));
    }
}

// ---------------------------------------------------------------------------
// Launch. Input order (R6-confirmed dict order):
//   0:x 1:y 2:Wq 3:bq 4:Wk 5:bk 6:Wv 7:bv 8:Wo 9:bo
// ---------------------------------------------------------------------------
extern "C" void kernel_launch(void* const* d_in, const int* in_sizes, int n_in,
                              void* d_out, int out_size)
{
    (void)in_sizes; (void)n_in; (void)out_size;
    const float* x  = (const float*)d_in[0];
    const float* y  = (const float*)d_in[1];
    const float* Wq = (const float*)d_in[2];
    const float* bq = (const float*)d_in[3];
    const float* Wk = (const float*)d_in[4];
    const float* bk = (const float*)d_in[5];
    const float* Wv = (const float*)d_in[6];
    const float* bv = (const float*)d_in[7];
    const float* Wo = (const float*)d_in[8];
    const float* bo = (const float*)d_in[9];
    float* out = (float*)d_out;

    float *Qb, *Kb;
    cudaGetSymbolAddress((void**)&Qb, g_Q);
    cudaGetSymbolAddress((void**)&Kb, g_K);

    __nv_bfloat16 *xh, *xl, *yh, *yl, *Wqh, *Wql, *Wkh, *Wkl, *Wvh, *Wvl,
                  *Woh, *Wol, *AOh, *AOl, *Qsh, *Qsl, *Ksh, *Ksl, *Vsh, *Vsl;
    cudaGetSymbolAddress((void**)&xh, g_xh);   cudaGetSymbolAddress((void**)&xl, g_xl);
    cudaGetSymbolAddress((void**)&yh, g_yh);   cudaGetSymbolAddress((void**)&yl, g_yl);
    cudaGetSymbolAddress((void**)&Wqh, g_Wqh); cudaGetSymbolAddress((void**)&Wql, g_Wql);
    cudaGetSymbolAddress((void**)&Wkh, g_Wkh); cudaGetSymbolAddress((void**)&Wkl, g_Wkl);
    cudaGetSymbolAddress((void**)&Wvh, g_Wvh); cudaGetSymbolAddress((void**)&Wvl, g_Wvl);
    cudaGetSymbolAddress((void**)&Woh, g_Woh); cudaGetSymbolAddress((void**)&Wol, g_Wol);
    cudaGetSymbolAddress((void**)&AOh, g_AOh); cudaGetSymbolAddress((void**)&AOl, g_AOl);
    cudaGetSymbolAddress((void**)&Qsh, g_Qh);  cudaGetSymbolAddress((void**)&Qsl, g_Ql);
    cudaGetSymbolAddress((void**)&Ksh, g_Kh);  cudaGetSymbolAddress((void**)&Ksl, g_Kl);
    cudaGetSymbolAddress((void**)&Vsh, g_Vh);  cudaGetSymbolAddress((void**)&Vsl, g_Vl);

    cudaFuncSetAttribute(qkv_gemm_kernel, cudaFuncAttributeMaxDynamicSharedMemorySize, GEMM_SMEM);
    cudaFuncSetAttribute(gemm_mma_kernel, cudaFuncAttributeMaxDynamicSharedMemorySize, GEMM_SMEM);
    const int smem_attn = (2 * QT * DSTR + 4 * KT * DSTR + 2 * QT * PSTR) * 2;
    cudaFuncSetAttribute(attn_mma_kernel, cudaFuncAttributeMaxDynamicSharedMemorySize, smem_attn);

    // RoPE table (independent)
    rope_table_kernel<<<(S_LEN * GVS + 255) / 256, 256>>>();

    // Mega-split: x, y, Wq, Wk, Wv, Wo in one launch
    {
        SplitArgs a;
        const float* srcs[6] = {x, y, Wq, Wk, Wv, Wo};
        __nv_bfloat16* his[6] = {xh, yh, Wqh, Wkh, Wvh, Woh};
        __nv_bfloat16* los[6] = {xl, yl, Wql, Wkl, Wvl, Wol};
        int ns[6] = {S_LEN * D_MODEL, S_LEN * D_MODEL,
                     D_MODEL * D_MODEL, D_MODEL * GS_DIM,
                     D_MODEL * GS_DIM, D_MODEL * D_MODEL};
        int acc = 0;
        for (int i = 0; i < 6; i++) {
            a.src[i] = srcs[i]; a.hi[i] = his[i]; a.lo[i] = los[i];
            a.off[i] = acc; acc += ns[i];
        }
        a.off[6] = acc;
        mega_split_kernel<<<(acc + 255) / 256, 256>>>(a);
    }

    // Fused QKV projection (384 CTAs; V emits split bf16 directly)
    {
        QKVArgs a;
        a.xh = xh; a.xl = xl; a.yh = yh; a.yl = yl;
        a.Wqh = Wqh; a.Wql = Wql; a.Wkh = Wkh; a.Wkl = Wkl; a.Wvh = Wvh; a.Wvl = Wvl;
        a.bq = bq; a.bk = bk; a.bv = bv;
        a.Q = Qb; a.K = Kb; a.Vh = Vsh; a.Vl = Vsl;
        qkv_gemm_kernel<<<384, 256, GEMM_SMEM>>>(a);
    }

    // Fused RoPE + split for Q and K (one launch)
    {
        RopeArgs a;
        a.Q = Qb; a.K = Kb;
        a.Qh = Qsh; a.Ql = Qsl; a.Kh = Ksh; a.Kl = Ksl;
        int tot = S_LEN * (N_HEAD + KV_HEAD) * GVS;
        rope_split_kernel<<<(tot + 255) / 256, 256>>>(a);
    }

    // MMA flash attention -> split bf16 AO
    attn_mma_kernel<<<dim3(S_LEN / QT, N_HEAD), 256, smem_attn>>>(
        Qsh, Qsl, Ksh, Ksl, Vsh, Vsl, AOh, AOl);

    // Output projection
    gemm_mma_kernel<<<dim3(D_MODEL / BN, S_LEN / BM), 256, GEMM_SMEM>>>(
        AOh, AOl, Woh, Wol, bo, out, D_MODEL, D_MODEL);
}

// round 15
// speedup vs baseline: 1.1668x; 1.1664x over previous
#include <cuda_runtime.h>
#include <cuda_bf16.h>
#include <math.h>
#include <stdint.h>

// ---------------------------------------------------------------------------
// Problem constants (B=1, S=2048, D=4096, n_head=32, kv_head=8, hd=128)
// ---------------------------------------------------------------------------
#define S_LEN 2048
#define D_MODEL 4096
#define GS_DIM 1024
#define N_HEAD 32
#define KV_HEAD 8
#define HEAD_DIM 128
#define GVS 64

// fp32 scratch
__device__ float g_Q[S_LEN * D_MODEL];
__device__ float g_K[S_LEN * GS_DIM];
__device__ float2 g_tab[S_LEN * GVS];

// bf16 hi/lo splits
__device__ __nv_bfloat16 g_xh[S_LEN * D_MODEL],  g_xl[S_LEN * D_MODEL];
__device__ __nv_bfloat16 g_yh[S_LEN * D_MODEL],  g_yl[S_LEN * D_MODEL];
__device__ __nv_bfloat16 g_Wqh[D_MODEL * D_MODEL], g_Wql[D_MODEL * D_MODEL];
__device__ __nv_bfloat16 g_Wkh[D_MODEL * GS_DIM],  g_Wkl[D_MODEL * GS_DIM];
__device__ __nv_bfloat16 g_Wvh[D_MODEL * GS_DIM],  g_Wvl[D_MODEL * GS_DIM];
__device__ __nv_bfloat16 g_Woh[D_MODEL * D_MODEL], g_Wol[D_MODEL * D_MODEL];
__device__ __nv_bfloat16 g_AOh[S_LEN * D_MODEL],   g_AOl[S_LEN * D_MODEL];
__device__ __nv_bfloat16 g_Qh[S_LEN * D_MODEL],    g_Ql[S_LEN * D_MODEL];
__device__ __nv_bfloat16 g_Kh[S_LEN * GS_DIM],     g_Kl[S_LEN * GS_DIM];
__device__ __nv_bfloat16 g_Vh[S_LEN * GS_DIM],     g_Vl[S_LEN * GS_DIM];

// ---------------------------------------------------------------------------
// Mega-split, 4 elements/thread (all segment sizes are multiples of 4).
// ---------------------------------------------------------------------------
struct SplitArgs {
    const float* src[6];
    __nv_bfloat16* hi[6];
    __nv_bfloat16* lo[6];
    int off[7];   // prefix sums in unit of 4-element chunks
};

__global__ void mega_split_kernel(SplitArgs a)
{
    int i = blockIdx.x * blockDim.x + threadIdx.x;   // chunk index
    if (i >= a.off[6]) return;
    int s = 0;
#pragma unroll
    for (int t = 1; t < 6; t++) s += (i >= a.off[t]);
    int j = (i - a.off[s]) * 4;
    float4 v = *(const float4*)(a.src[s] + j);
    __nv_bfloat16 h0 = __float2bfloat16(v.x);
    __nv_bfloat16 h1 = __float2bfloat16(v.y);
    __nv_bfloat16 h2 = __float2bfloat16(v.z);
    __nv_bfloat16 h3 = __float2bfloat16(v.w);
    __nv_bfloat162 hi01(h0, h1), hi23(h2, h3);
    __nv_bfloat162 lo01(__float2bfloat16(v.x - __bfloat162float(h0)),
                        __float2bfloat16(v.y - __bfloat162float(h1)));
    __nv_bfloat162 lo23(__float2bfloat16(v.z - __bfloat162float(h2)),
                        __float2bfloat16(v.w - __bfloat162float(h3)));
    *(uint2*)(a.hi[s] + j) = make_uint2(*(uint32_t*)&hi01, *(uint32_t*)&hi23);
    *(uint2*)(a.lo[s] + j) = make_uint2(*(uint32_t*)&lo01, *(uint32_t*)&lo23);
}

// Filler so the ncu capture (launch idx 3) lands on the QKV GEMM.
__global__ void noop_kernel() {}

// ---------------------------------------------------------------------------
// MMA helpers
// ---------------------------------------------------------------------------
__device__ __forceinline__ void ldmx4(uint32_t* r, const void* p)
{
    uint32_t a = (uint32_t)__cvta_generic_to_shared(p);
    asm volatile("ldmatrix.sync.aligned.m8n8.x4.shared.b16 {%0,%1,%2,%3}, [%4];"
                 : "=r"(r[0]), "=r"(r[1]), "=r"(r[2]), "=r"(r[3]) : "r"(a));
}
__device__ __forceinline__ void ldmx4t(uint32_t* r, const void* p)
{
    uint32_t a = (uint32_t)__cvta_generic_to_shared(p);
    asm volatile("ldmatrix.sync.aligned.m8n8.x4.trans.shared.b16 {%0,%1,%2,%3}, [%4];"
                 : "=r"(r[0]), "=r"(r[1]), "=r"(r[2]), "=r"(r[3]) : "r"(a));
}
__device__ __forceinline__ void mma16816(float* d, const uint32_t* a,
                                         uint32_t b0, uint32_t b1)
{
    asm volatile(
        "mma.sync.aligned.m16n8k16.row.col.f32.bf16.bf16.f32 "
        "{%0,%1,%2,%3}, {%4,%5,%6,%7}, {%8,%9}, {%0,%1,%2,%3};"
        : "+f"(d[0]), "+f"(d[1]), "+f"(d[2]), "+f"(d[3])
        : "r"(a[0]), "r"(a[1]), "r"(a[2]), "r"(a[3]), "r"(b0), "r"(b1));
}
__device__ __forceinline__ void cpasync16(void* smem, const void* gmem)
{
    uint32_t a = (uint32_t)__cvta_generic_to_shared(smem);
    asm volatile("cp.async.cg.shared.global [%0], [%1], 16;" :: "r"(a), "l"(gmem));
}
#define CP_COMMIT() asm volatile("cp.async.commit_group;")
#define CP_WAIT1()  asm volatile("cp.async.wait_group 1;")

// ---------------------------------------------------------------------------
// Split-bf16 3-pass GEMM tile (R12 config: CTA 128x128, BK=32, warps 64x32).
// Double-buffered cp.async. Output fp32 (C) or split bf16 (Ch/Cl if C==null).
// ---------------------------------------------------------------------------
#define BM 128
#define BN 128
#define BK 32
#define A_STRIDE 40
#define B_STRIDE 136
#define ASZ (BM * A_STRIDE)
#define BSZ (BK * B_STRIDE)
#define STG (2 * ASZ + 2 * BSZ)
#define GEMM_SMEM (2 * STG * 2)   // ~74 KB

__device__ __forceinline__ void gemm_tile(
    const __nv_bfloat16* __restrict__ Ah, const __nv_bfloat16* __restrict__ Al,
    const __nv_bfloat16* __restrict__ Bh, const __nv_bfloat16* __restrict__ Bl,
    const float* __restrict__ bias,
    float* __restrict__ C, __nv_bfloat16* __restrict__ Ch,
    __nv_bfloat16* __restrict__ Cl,
    int N, int K, int m0, int n0, __nv_bfloat16* sm)
{
    const int tid  = threadIdx.x;
    const int lane = tid & 31;
    const int wid  = tid >> 5;
    const int wm   = (wid >> 2) * 64;
    const int wn   = (wid & 3) * 32;

    const int ar = tid >> 1;
    const int ac = (tid & 1) * 8;
    const int br0 = tid >> 4, bc0 = (tid & 15) * 8;
    const int br1 = br0 + 16;

    float acc[4][4][4];
#pragma unroll
    for (int i = 0; i < 4; i++)
#pragma unroll
        for (int j = 0; j < 4; j++)
#pragma unroll
            for (int v = 0; v < 4; v++) acc[i][j][v] = 0.0f;

#define PREFETCH(st, k0)                                                          \
    do {                                                                          \
        __nv_bfloat16* aH = sm + (st) * STG;                                      \
        __nv_bfloat16* aL = aH + ASZ;                                             \
        __nv_bfloat16* bH = aL + ASZ;                                             \
        __nv_bfloat16* bL = bH + BSZ;                                             \
        const __nv_bfloat16* gah = Ah + (size_t)(m0 + ar) * K + (k0) + ac;        \
        const __nv_bfloat16* gal = Al + (size_t)(m0 + ar) * K + (k0) + ac;        \
        cpasync16(aH + ar * A_STRIDE + ac,      gah);                             \
        cpasync16(aH + ar * A_STRIDE + ac + 16, gah + 16);                        \
        cpasync16(aL + ar * A_STRIDE + ac,      gal);                             \
        cpasync16(aL + ar * A_STRIDE + ac + 16, gal + 16);                        \
        cpasync16(bH + br0 * B_STRIDE + bc0, Bh + (size_t)((k0) + br0) * N + n0 + bc0); \
        cpasync16(bH + br1 * B_STRIDE + bc0, Bh + (size_t)((k0) + br1) * N + n0 + bc0); \
        cpasync16(bL + br0 * B_STRIDE + bc0, Bl + (size_t)((k0) + br0) * N + n0 + bc0); \
        cpasync16(bL + br1 * B_STRIDE + bc0, Bl + (size_t)((k0) + br1) * N + n0 + bc0); \
    } while (0)

    const int nk = K / BK;
    PREFETCH(0, 0);
    CP_COMMIT();

    const int lrow = lane & 15;
    const int lcol = (lane >> 4) * 8;

    for (int i = 0; i < nk; i++) {
        if (i + 1 < nk) PREFETCH((i + 1) & 1, (i + 1) * BK);
        CP_COMMIT();
        CP_WAIT1();
        __syncthreads();

        const int st = i & 1;
        __nv_bfloat16* aH = sm + st * STG;
        __nv_bfloat16* aL = aH + ASZ;
        __nv_bfloat16* bH = aL + ASZ;
        __nv_bfloat16* bL = bH + BSZ;

#pragma unroll
        for (int kk = 0; kk < BK; kk += 16) {
            uint32_t ah[4][4], al[4][4], bh[2][4], bl[2][4];
#pragma unroll
            for (int mt = 0; mt < 4; mt++) {
                ldmx4(ah[mt], aH + (wm + mt * 16 + lrow) * A_STRIDE + kk + lcol);
                ldmx4(al[mt], aL + (wm + mt * 16 + lrow) * A_STRIDE + kk + lcol);
            }
#pragma unroll
            for (int ntp = 0; ntp < 2; ntp++) {
                ldmx4t(bh[ntp], bH + (kk + lrow) * B_STRIDE + wn + ntp * 16 + lcol);
                ldmx4t(bl[ntp], bL + (kk + lrow) * B_STRIDE + wn + ntp * 16 + lcol);
            }
#pragma unroll
            for (int mt = 0; mt < 4; mt++)
#pragma unroll
                for (int nt = 0; nt < 4; nt++) {
                    const int ntp = nt >> 1, off = (nt & 1) * 2;
                    mma16816(acc[mt][nt], ah[mt], bh[ntp][off], bh[ntp][off + 1]);
                    mma16816(acc[mt][nt], ah[mt], bl[ntp][off], bl[ntp][off + 1]);
                    mma16816(acc[mt][nt], al[mt], bh[ntp][off], bh[ntp][off + 1]);
                }
        }
        __syncthreads();
    }
#undef PREFETCH

    const int er = lane >> 2;
    const int ec = (lane & 3) * 2;
#pragma unroll
    for (int mt = 0; mt < 4; mt++)
#pragma unroll
        for (int nt = 0; nt < 4; nt++) {
            int r0 = m0 + wm + mt * 16 + er;
            int c0 = n0 + wn + nt * 8 + ec;
            float b0 = bias[c0], b1 = bias[c0 + 1];
            float v0 = acc[mt][nt][0] + b0, v1 = acc[mt][nt][1] + b1;
            float v2 = acc[mt][nt][2] + b0, v3 = acc[mt][nt][3] + b1;
            if (C) {
                *(float2*)(C + (size_t)r0 * N + c0) = make_float2(v0, v1);
                *(float2*)(C + (size_t)(r0 + 8) * N + c0) = make_float2(v2, v3);
            } else {
                __nv_bfloat16 h0 = __float2bfloat16(v0), h1 = __float2bfloat16(v1);
                __nv_bfloat16 h2 = __float2bfloat16(v2), h3 = __float2bfloat16(v3);
                *(__nv_bfloat162*)(Ch + (size_t)r0 * N + c0) = __nv_bfloat162(h0, h1);
                *(__nv_bfloat162*)(Ch + (size_t)(r0 + 8) * N + c0) = __nv_bfloat162(h2, h3);
                *(__nv_bfloat162*)(Cl + (size_t)r0 * N + c0) =
                    __nv_bfloat162(__float2bfloat16(v0 - __bfloat162float(h0)),
                                   __float2bfloat16(v1 - __bfloat162float(h1)));
                *(__nv_bfloat162*)(Cl + (size_t)(r0 + 8) * N + c0) =
                    __nv_bfloat162(__float2bfloat16(v2 - __bfloat162float(h2)),
                                   __float2bfloat16(v3 - __bfloat162float(h3)));
            }
        }
}

// ---------------------------------------------------------------------------
// Fused QKV GEMM: 768 CTAs (Q:512, K:128, V:128). V emits split bf16.
// ---------------------------------------------------------------------------
struct QKVArgs {
    const __nv_bfloat16 *xh, *xl, *yh, *yl;
    const __nv_bfloat16 *Wqh, *Wql, *Wkh, *Wkl, *Wvh, *Wvl;
    const float *bq, *bk, *bv;
    float *Q, *K;
    __nv_bfloat16 *Vh, *Vl;
};

__global__ __launch_bounds__(256) void qkv_gemm_kernel(QKVArgs a)
{
    extern __shared__ __nv_bfloat16 sm[];
    int bid = blockIdx.x;
    if (bid < 512) {
        gemm_tile(a.xh, a.xl, a.Wqh, a.Wql, a.bq,
                  a.Q, nullptr, nullptr,
                  D_MODEL, D_MODEL, (bid >> 5) * BM, (bid & 31) * BN, sm);
    } else if (bid < 640) {
        int t = bid - 512;
        gemm_tile(a.yh, a.yl, a.Wkh, a.Wkl, a.bk,
                  a.K, nullptr, nullptr,
                  GS_DIM, D_MODEL, (t >> 3) * BM, (t & 7) * BN, sm);
    } else {
        int t = bid - 640;
        gemm_tile(a.yh, a.yl, a.Wvh, a.Wvl, a.bv,
                  nullptr, a.Vh, a.Vl,
                  GS_DIM, D_MODEL, (t >> 3) * BM, (t & 7) * BN, sm);
    }
}

// Standalone GEMM (output projection), fp32 out
__global__ __launch_bounds__(256) void gemm_mma_kernel(
    const __nv_bfloat16* __restrict__ Ah, const __nv_bfloat16* __restrict__ Al,
    const __nv_bfloat16* __restrict__ Bh, const __nv_bfloat16* __restrict__ Bl,
    const float* __restrict__ bias, float* __restrict__ C, int N, int K)
{
    extern __shared__ __nv_bfloat16 sm[];
    gemm_tile(Ah, Al, Bh, Bl, bias, C, nullptr, nullptr,
              N, K, blockIdx.y * BM, blockIdx.x * BN, sm);
}

// ---------------------------------------------------------------------------
// RoPE: table, then one fused rotate+split launch covering Q and K
// ---------------------------------------------------------------------------
__global__ void rope_table_kernel()
{
    int idx = blockIdx.x * blockDim.x + threadIdx.x;
    if (idx >= S_LEN * GVS) return;
    int s = idx / GVS, i = idx % GVS;
    double phi = exp(-((double)i / (double)GVS) * log(5000.0));
    double sn, c;
    sincos((double)s * phi, &sn, &c);   // sin first, cos second
    g_tab[idx] = make_float2((float)c, (float)sn);
}

struct RopeArgs {
    const float *Q, *K;
    __nv_bfloat16 *Qh, *Ql, *Kh, *Kl;
};

__global__ void rope_split_kernel(RopeArgs a)
{
    const int qtot = S_LEN * N_HEAD * GVS;
    const int ktot = S_LEN * KV_HEAD * GVS;
    int idx = blockIdx.x * blockDim.x + threadIdx.x;
    if (idx >= qtot + ktot) return;

    const float* T; __nv_bfloat16 *hi, *lo;
    int H; float scale;
    if (idx < qtot) {
        T = a.Q; hi = a.Qh; lo = a.Ql; H = N_HEAD;
        scale = 0.08838834764831845f;
    } else {
        idx -= qtot;
        T = a.K; hi = a.Kh; lo = a.Kl; H = KV_HEAD;
        scale = 1.0f;
    }
    int i = idx % GVS;
    int h = (idx / GVS) % H;
    int s = idx / (GVS * H);
    float2 cs = g_tab[s * GVS + i];
    size_t base = ((size_t)s * H + h) * HEAD_DIM + 2 * i;
    float tr = T[base], ti = T[base + 1];
    float ro = (tr * cs.x - ti * cs.y) * scale;
    float io = (tr * cs.y + ti * cs.x) * scale;
    __nv_bfloat16 h0 = __float2bfloat16(ro);
    __nv_bfloat16 h1 = __float2bfloat16(io);
    hi[base]     = h0;
    hi[base + 1] = h1;
    lo[base]     = __float2bfloat16(ro - __bfloat162float(h0));
    lo[base + 1] = __float2bfloat16(io - __bfloat162float(h1));
}

// ---------------------------------------------------------------------------
// MMA flash attention (split bf16 in/out). Heavy q-tiles first.
// ---------------------------------------------------------------------------
#define QT 128
#define KT 64
#define DSTR 136
#define PSTR 72

__global__ __launch_bounds__(256) void attn_mma_kernel(
    const __nv_bfloat16* __restrict__ Qh, const __nv_bfloat16* __restrict__ Ql,
    const __nv_bfloat16* __restrict__ Kh, const __nv_bfloat16* __restrict__ Kl,
    const __nv_bfloat16* __restrict__ Vh, const __nv_bfloat16* __restrict__ Vl,
    __nv_bfloat16* __restrict__ Oh, __nv_bfloat16* __restrict__ Ol)
{
    extern __shared__ __nv_bfloat16 sb[];
    __nv_bfloat16* sQh = sb;
    __nv_bfloat16* sQl = sQh + QT * DSTR;
    __nv_bfloat16* sKh = sQl + QT * DSTR;
    __nv_bfloat16* sKl = sKh + KT * DSTR;
    __nv_bfloat16* sVh = sKl + KT * DSTR;
    __nv_bfloat16* sVl = sVh + KT * DSTR;
    __nv_bfloat16* sPh = sVl + KT * DSTR;
    __nv_bfloat16* sPl = sPh + QT * PSTR;

    const int tid  = threadIdx.x;
    const int lane = tid & 31;
    const int wid  = tid >> 5;
    const int wrow = wid * 16;
    const int qt   = (gridDim.x - 1) - blockIdx.x;
    const int h    = blockIdx.y;
    const int q0   = qt * QT;
    const int kvh  = h >> 2;

    for (int t = tid; t < QT * 16; t += 256) {
        int r = t >> 4, c8 = (t & 15) * 8;
        const uint4* ph = (const uint4*)(Qh + (size_t)(q0 + r) * D_MODEL + h * HEAD_DIM + c8);
        const uint4* pl = (const uint4*)(Ql + (size_t)(q0 + r) * D_MODEL + h * HEAD_DIM + c8);
        *(uint4*)(sQh + r * DSTR + c8) = *ph;
        *(uint4*)(sQl + r * DSTR + c8) = *pl;
    }

    float oacc[16][4];
#pragma unroll
    for (int nt = 0; nt < 16; nt++)
#pragma unroll
        for (int v = 0; v < 4; v++) oacc[nt][v] = 0.0f;
    float m_lo = -1e30f, m_hi = -1e30f, l_lo = 0.0f, l_hi = 0.0f;

    const int lrow = lane & 15;
    const int lcol = (lane >> 4) * 8;
    const int er   = lane >> 2;
    const int ec   = (lane & 3) * 2;

    const int ktmax = 2 * qt + 1;
    for (int kt = 0; kt <= ktmax; kt++) {
        const int k0 = kt * KT;
        __syncthreads();
        for (int t = tid; t < KT * 16; t += 256) {
            int r = t >> 4, c8 = (t & 15) * 8;
            size_t g = (size_t)(k0 + r) * GS_DIM + kvh * HEAD_DIM + c8;
            *(uint4*)(sKh + r * DSTR + c8) = *(const uint4*)(Kh + g);
            *(uint4*)(sKl + r * DSTR + c8) = *(const uint4*)(Kl + g);
            *(uint4*)(sVh + r * DSTR + c8) = *(const uint4*)(Vh + g);
            *(uint4*)(sVl + r * DSTR + c8) = *(const uint4*)(Vl + g);
        }
        __syncthreads();

        if (k0 > q0 + wrow + 15) continue;

        float sacc[8][4];
#pragma unroll
        for (int nt = 0; nt < 8; nt++)
#pragma unroll
            for (int v = 0; v < 4; v++) sacc[nt][v] = 0.0f;

#pragma unroll
        for (int kk = 0; kk < 8; kk++) {
            uint32_t ah[4], al[4];
            ldmx4(ah, sQh + (wrow + lrow) * DSTR + kk * 16 + lcol);
            ldmx4(al, sQl + (wrow + lrow) * DSTR + kk * 16 + lcol);
#pragma unroll
            for (int np = 0; np < 4; np++) {
                uint32_t bh[4], bl[4];
                ldmx4(bh, sKh + (np * 16 + lrow) * DSTR + kk * 16 + lcol);
                ldmx4(bl, sKl + (np * 16 + lrow) * DSTR + kk * 16 + lcol);
                mma16816(sacc[2 * np],     ah, bh[0], bh[2]);
                mma16816(sacc[2 * np],     ah, bl[0], bl[2]);
                mma16816(sacc[2 * np],     al, bh[0], bh[2]);
                mma16816(sacc[2 * np + 1], ah, bh[1], bh[3]);
                mma16816(sacc[2 * np + 1], ah, bl[1], bl[3]);
                mma16816(sacc[2 * np + 1], al, bh[1], bh[3]);
            }
        }

        if (kt >= 2 * qt) {
            int gq_lo = q0 + wrow + er;
            int gq_hi = gq_lo + 8;
#pragma unroll
            for (int nt = 0; nt < 8; nt++) {
                int c0 = k0 + nt * 8 + ec;
                if (c0 > gq_lo)     sacc[nt][0] = -1e30f;
                if (c0 + 1 > gq_lo) sacc[nt][1] = -1e30f;
                if (c0 > gq_hi)     sacc[nt][2] = -1e30f;
                if (c0 + 1 > gq_hi) sacc[nt][3] = -1e30f;
            }
        }

        float mx_lo = -1e30f, mx_hi = -1e30f;
#pragma unroll
        for (int nt = 0; nt < 8; nt++) {
            mx_lo = fmaxf(mx_lo, fmaxf(sacc[nt][0], sacc[nt][1]));
            mx_hi = fmaxf(mx_hi, fmaxf(sacc[nt][2], sacc[nt][3]));
        }
        mx_lo = fmaxf(mx_lo, __shfl_xor_sync(0xffffffffu, mx_lo, 1));
        mx_lo = fmaxf(mx_lo, __shfl_xor_sync(0xffffffffu, mx_lo, 2));
        mx_hi = fmaxf(mx_hi, __shfl_xor_sync(0xffffffffu, mx_hi, 1));
        mx_hi = fmaxf(mx_hi, __shfl_xor_sync(0xffffffffu, mx_hi, 2));

        float mn_lo = fmaxf(m_lo, mx_lo);
        float mn_hi = fmaxf(m_hi, mx_hi);
        float al_lo = __expf(m_lo - mn_lo);
        float al_hi = __expf(m_hi - mn_hi);

        float sum_lo = 0.0f, sum_hi = 0.0f;
#pragma unroll
        for (int nt = 0; nt < 8; nt++) {
            float p0 = __expf(sacc[nt][0] - mn_lo);
            float p1 = __expf(sacc[nt][1] - mn_lo);
            float p2 = __expf(sacc[nt][2] - mn_hi);
            float p3 = __expf(sacc[nt][3] - mn_hi);
            sum_lo += p0 + p1;
            sum_hi += p2 + p3;
            int c = nt * 8 + ec;
            __nv_bfloat16 h0 = __float2bfloat16(p0);
            __nv_bfloat16 h1 = __float2bfloat16(p1);
            __nv_bfloat16 h2 = __float2bfloat16(p2);
            __nv_bfloat16 h3 = __float2bfloat16(p3);
            sPh[(wrow + er) * PSTR + c]     = h0;
            sPh[(wrow + er) * PSTR + c + 1] = h1;
            sPh[(wrow + er + 8) * PSTR + c]     = h2;
            sPh[(wrow + er + 8) * PSTR + c + 1] = h3;
            sPl[(wrow + er) * PSTR + c]     = __float2bfloat16(p0 - __bfloat162float(h0));
            sPl[(wrow + er) * PSTR + c + 1] = __float2bfloat16(p1 - __bfloat162float(h1));
            sPl[(wrow + er + 8) * PSTR + c]     = __float2bfloat16(p2 - __bfloat162float(h2));
            sPl[(wrow + er + 8) * PSTR + c + 1] = __float2bfloat16(p3 - __bfloat162float(h3));
        }
        sum_lo += __shfl_xor_sync(0xffffffffu, sum_lo, 1);
        sum_lo += __shfl_xor_sync(0xffffffffu, sum_lo, 2);
        sum_hi += __shfl_xor_sync(0xffffffffu, sum_hi, 1);
        sum_hi += __shfl_xor_sync(0xffffffffu, sum_hi, 2);

        l_lo = l_lo * al_lo + sum_lo;
        l_hi = l_hi * al_hi + sum_hi;
        m_lo = mn_lo; m_hi = mn_hi;

#pragma unroll
        for (int nt = 0; nt < 16; nt++) {
            oacc[nt][0] *= al_lo; oacc[nt][1] *= al_lo;
            oacc[nt][2] *= al_hi; oacc[nt][3] *= al_hi;
        }
        __syncwarp();

#pragma unroll
        for (int kk = 0; kk < 4; kk++) {
            uint32_t ah[4], al2[4];
            ldmx4(ah,  sPh + (wrow + lrow) * PSTR + kk * 16 + lcol);
            ldmx4(al2, sPl + (wrow + lrow) * PSTR + kk * 16 + lcol);
#pragma unroll
            for (int np = 0; np < 8; np++) {
                uint32_t bh[4], bl[4];
                ldmx4t(bh, sVh + (kk * 16 + lrow) * DSTR + np * 16 + lcol);
                ldmx4t(bl, sVl + (kk * 16 + lrow) * DSTR + np * 16 + lcol);
                mma16816(oacc[2 * np],     ah,  bh[0], bh[1]);
                mma16816(oacc[2 * np],     al2, bh[0], bh[1]);
                mma16816(oacc[2 * np],     ah,  bl[0], bl[1]);
                mma16816(oacc[2 * np + 1], ah,  bh[2], bh[3]);
                mma16816(oacc[2 * np + 1], al2, bh[2], bh[3]);
                mma16816(oacc[2 * np + 1], ah,  bl[2], bl[3]);
            }
        }
    }

    float inv_lo = 1.0f / l_lo;
    float inv_hi = 1.0f / l_hi;
    int gq_lo = q0 + wrow + er;
#pragma unroll
    for (int nt = 0; nt < 16; nt++) {
        int c = h * HEAD_DIM + nt * 8 + ec;
        float v0 = oacc[nt][0] * inv_lo, v1 = oacc[nt][1] * inv_lo;
        float v2 = oacc[nt][2] * inv_hi, v3 = oacc[nt][3] * inv_hi;
        __nv_bfloat16 h0 = __float2bfloat16(v0), h1 = __float2bfloat16(v1);
        __nv_bfloat16 h2 = __float2bfloat16(v2), h3 = __float2bfloat16(v3);
        __nv_bfloat162* p;
        p = (__nv_bfloat162*)(Oh + (size_t)gq_lo * D_MODEL + c);
        *p = __nv_bfloat162(h0, h1);
        p = (__nv_bfloat162*)(Oh + (size_t)(gq_lo + 8) * D_MODEL + c);
        *p = __nv_bfloat162(h2, h3);
        p = (__nv_bfloat162*)(Ol + (size_t)gq_lo * D_MODEL + c);
        *p = __nv_bfloat162(__float2bfloat16(v0 - __bfloat162float(h0)),
                            __float2bfloat16(v1 - __bfloat162float(h1)));
        p = (__nv_bfloat162*)(Ol + (size_t)(gq_lo + 8) * D_MODEL + c);
        *p = __nv_bfloat162(__float2bfloat16(v2 - __bfloat162float(h2)),
                            __float2bfloat16(v3 - __bfloat162float(h3)));
    }
}

// ---------------------------------------------------------------------------
// Launch. Input order (R6-confirmed dict order):
//   0:x 1:y 2:Wq 3:bq 4:Wk 5:bk 6:Wv 7:bv 8:Wo 9:bo
// Launch order: rope_table(0), mega_split(1), noop(2), qkv(3) <- ncu target,
//               rope_split(4), attn(5), wo(6)
// ---------------------------------------------------------------------------
extern "C" void kernel_launch(void* const* d_in, const int* in_sizes, int n_in,
                              void* d_out, int out_size)
{
    (void)in_sizes; (void)n_in; (void)out_size;
    const float* x  = (const float*)d_in[0];
    const float* y  = (const float*)d_in[1];
    const float* Wq = (const float*)d_in[2];
    const float* bq = (const float*)d_in[3];
    const float* Wk = (const float*)d_in[4];
    const float* bk = (const float*)d_in[5];
    const float* Wv = (const float*)d_in[6];
    const float* bv = (const float*)d_in[7];
    const float* Wo = (const float*)d_in[8];
    const float* bo = (const float*)d_in[9];
    float* out = (float*)d_out;

    float *Qb, *Kb;
    cudaGetSymbolAddress((void**)&Qb, g_Q);
    cudaGetSymbolAddress((void**)&Kb, g_K);

    __nv_bfloat16 *xh, *xl, *yh, *yl, *Wqh, *Wql, *Wkh, *Wkl, *Wvh, *Wvl,
                  *Woh, *Wol, *AOh, *AOl, *Qsh, *Qsl, *Ksh, *Ksl, *Vsh, *Vsl;
    cudaGetSymbolAddress((void**)&xh, g_xh);   cudaGetSymbolAddress((void**)&xl, g_xl);
    cudaGetSymbolAddress((void**)&yh, g_yh);   cudaGetSymbolAddress((void**)&yl, g_yl);
    cudaGetSymbolAddress((void**)&Wqh, g_Wqh); cudaGetSymbolAddress((void**)&Wql, g_Wql);
    cudaGetSymbolAddress((void**)&Wkh, g_Wkh); cudaGetSymbolAddress((void**)&Wkl, g_Wkl);
    cudaGetSymbolAddress((void**)&Wvh, g_Wvh); cudaGetSymbolAddress((void**)&Wvl, g_Wvl);
    cudaGetSymbolAddress((void**)&Woh, g_Woh); cudaGetSymbolAddress((void**)&Wol, g_Wol);
    cudaGetSymbolAddress((void**)&AOh, g_AOh); cudaGetSymbolAddress((void**)&AOl, g_AOl);
    cudaGetSymbolAddress((void**)&Qsh, g_Qh);  cudaGetSymbolAddress((void**)&Qsl, g_Ql);
    cudaGetSymbolAddress((void**)&Ksh, g_Kh);  cudaGetSymbolAddress((void**)&Ksl, g_Kl);
    cudaGetSymbolAddress((void**)&Vsh, g_Vh);  cudaGetSymbolAddress((void**)&Vsl, g_Vl);

    cudaFuncSetAttribute(qkv_gemm_kernel, cudaFuncAttributeMaxDynamicSharedMemorySize, GEMM_SMEM);
    cudaFuncSetAttribute(gemm_mma_kernel, cudaFuncAttributeMaxDynamicSharedMemorySize, GEMM_SMEM);
    const int smem_attn = (2 * QT * DSTR + 4 * KT * DSTR + 2 * QT * PSTR) * 2;
    cudaFuncSetAttribute(attn_mma_kernel, cudaFuncAttributeMaxDynamicSharedMemorySize, smem_attn);

    // 0: RoPE table
    rope_table_kernel<<<(S_LEN * GVS + 255) / 256, 256>>>();

    // 1: mega-split (vectorized x4)
    {
        SplitArgs a;
        const float* srcs[6] = {x, y, Wq, Wk, Wv, Wo};
        __nv_bfloat16* his[6] = {xh, yh, Wqh, Wkh, Wvh, Woh};
        __nv_bfloat16* los[6] = {xl, yl, Wql, Wkl, Wvl, Wol};
        int ns[6] = {S_LEN * D_MODEL, S_LEN * D_MODEL,
                     D_MODEL * D_MODEL, D_MODEL * GS_DIM,
                     D_MODEL * GS_DIM, D_MODEL * D_MODEL};
        int acc = 0;
        for (int i = 0; i < 6; i++) {
            a.src[i] = srcs[i]; a.hi[i] = his[i]; a.lo[i] = los[i];
            a.off[i] = acc; acc += ns[i] / 4;   // chunk units
        }
        a.off[6] = acc;
        mega_split_kernel<<<(acc + 255) / 256, 256>>>(a);
    }

    // 2: filler so ncu (launch idx 3) profiles the QKV GEMM
    noop_kernel<<<1, 32>>>();

    // 3: fused QKV projection
    {
        QKVArgs a;
        a.xh = xh; a.xl = xl; a.yh = yh; a.yl = yl;
        a.Wqh = Wqh; a.Wql = Wql; a.Wkh = Wkh; a.Wkl = Wkl; a.Wvh = Wvh; a.Wvl = Wvl;
        a.bq = bq; a.bk = bk; a.bv = bv;
        a.Q = Qb; a.K = Kb; a.Vh = Vsh; a.Vl = Vsl;
        qkv_gemm_kernel<<<768, 256, GEMM_SMEM>>>(a);
    }

    // 4: fused RoPE + split
    {
        RopeArgs a;
        a.Q = Qb; a.K = Kb;
        a.Qh = Qsh; a.Ql = Qsl; a.Kh = Ksh; a.Kl = Ksl;
        int tot = S_LEN * (N_HEAD + KV_HEAD) * GVS;
        rope_split_kernel<<<(tot + 255) / 256, 256>>>(a);
    }

    // 5: MMA flash attention
    attn_mma_kernel<<<dim3(S_LEN / QT, N_HEAD), 256, smem_attn>>>(
        Qsh, Qsl, Ksh, Ksl, Vsh, Vsl, AOh, AOl);

    // 6: output projection
    gemm_mma_kernel<<<dim3(D_MODEL / BN, S_LEN / BM), 256, GEMM_SMEM>>>(
        AOh, AOl, Woh, Wol, bo, out, D_MODEL, D_MODEL);
}